// round 6
// baseline (speedup 1.0000x reference)
#include <cuda_runtime.h>
#include <cuda_bf16.h>
#include <mma.h>
#include <cstdint>

using namespace nvcuda;

#define BB   512
#define TT   128
#define DIN  256
#define HH   1024
#define FH   4096
#define TBROWS (TT*BB)

#define OPB 10240u            // one operand per stage: 128 rows * 80 bytes
#define OPE 5120              // same in bf16 elements
#define STG 40960u            // 4 operands per stage (bytes)
#define NSTAGE 5
#define SMEM_DYN (NSTAGE*40960)   // 200 KB
#define LDS_EP 132            // epilogue smem stride (floats)

// ------------- device scratch (no allocation allowed) -------------
__device__ float d_Z[(size_t)TBROWS*FH];
__device__ float d_c1[BB*HH], d_c2[BB*HH];
__device__ float d_hidden[BB*HH];
__device__ float d_b1i[FH], d_b2i[FH];
__device__ __nv_bfloat16 d_Xh[(size_t)TBROWS*DIN], d_Xl[(size_t)TBROWS*DIN];
__device__ __nv_bfloat16 d_H1h[(size_t)(TT+1)*BB*HH], d_H1l[(size_t)(TT+1)*BB*HH];
__device__ __nv_bfloat16 d_H2h[(size_t)(TT+1)*BB*HH], d_H2l[(size_t)(TT+1)*BB*HH];
__device__ __nv_bfloat16 d_W1h[(size_t)FH*DIN], d_W1l[(size_t)FH*DIN];
__device__ __nv_bfloat16 d_U1h[(size_t)FH*HH],  d_U1l[(size_t)FH*HH];
__device__ __nv_bfloat16 d_W2h[(size_t)FH*HH],  d_W2l[(size_t)FH*HH];
__device__ __nv_bfloat16 d_U2h[(size_t)FH*HH],  d_U2l[(size_t)FH*HH];

// ------------- PTX helpers (Ampere-level: valid on plain sm_103) ------
__device__ __forceinline__ uint32_t smem_u32(const void* p) {
    uint32_t a;
    asm("{ .reg .u64 t; cvta.to.shared.u64 t, %1; cvt.u32.u64 %0, t; }" : "=r"(a) : "l"(p));
    return a;
}
__device__ __forceinline__ void cp16(uint32_t d, const void* s) {
    asm volatile("cp.async.cg.shared.global [%0], [%1], 16;" :: "r"(d), "l"(s) : "memory");
}
__device__ __forceinline__ void cp_commit() { asm volatile("cp.async.commit_group;" ::: "memory"); }
__device__ __forceinline__ void cp_wait3()  { asm volatile("cp.async.wait_group 3;" ::: "memory"); }

// ------------- preprocessing -------------
// W [K, 4H] -> Wt[n=j*4+gate][k], split hi/lo bf16
__global__ void split_w(const float* __restrict__ W, __nv_bfloat16* __restrict__ oh,
                        __nv_bfloat16* __restrict__ ol, int K)
{
    size_t i = (size_t)blockIdx.x * blockDim.x + threadIdx.x;
    int k = (int)(i % K), n = (int)(i / K);
    float x = W[(size_t)k * FH + (n & 3) * HH + (n >> 2)];
    __nv_bfloat16 h = __float2bfloat16(x);
    oh[i] = h;
    ol[i] = __float2bfloat16(x - __bfloat162float(h));
}
__global__ void interleave_bias(const float* __restrict__ b, float* __restrict__ bi)
{
    int n = blockIdx.x * blockDim.x + threadIdx.x;
    bi[n] = b[(n & 3) * HH + (n >> 2)];
}
// chars [B][T][256] -> split bf16 time-major [t*B+b][256]
__global__ void split_chars(const float* __restrict__ chars,
                            __nv_bfloat16* __restrict__ xh, __nv_bfloat16* __restrict__ xl)
{
    int idx = blockIdx.x * blockDim.x + threadIdx.x;   // TBROWS*64
    int d4 = idx & 63, rest = idx >> 6;
    int b = rest & (BB - 1), t = rest >> 9;
    float4 v = *(const float4*)(chars + ((size_t)b * TT + t) * DIN + d4 * 4);
    size_t o = ((size_t)t * BB + b) * DIN + d4 * 4;
    float vv[4] = {v.x, v.y, v.z, v.w};
    #pragma unroll
    for (int e = 0; e < 4; e++) {
        __nv_bfloat16 h = __float2bfloat16(vv[e]);
        xh[o + e] = h;
        xl[o + e] = __float2bfloat16(vv[e] - __bfloat162float(h));
    }
}
__global__ void init_states()
{
    int i = blockIdx.x * blockDim.x + threadIdx.x;  // BB*HH
    d_c1[i] = 0.f; d_c2[i] = 0.f;
    __nv_bfloat16 z = __float2bfloat16(0.f);
    d_H1h[i] = z; d_H1l[i] = z; d_H2h[i] = z; d_H2l[i] = z;
}
__global__ void dense_relu(const float* __restrict__ hidden, const float* __restrict__ Wd,
                           const float* __restrict__ bd, float* __restrict__ out)
{
    __shared__ float buf[3][128];
    int b = blockIdx.x, tid = threadIdx.x;
    const float* hb = hidden + (size_t)b * HH;
    float s0 = 0.f, s1 = 0.f, s2 = 0.f;
    for (int k = tid; k < HH; k += 128) {
        float hv = hb[k];
        s0 = fmaf(hv, Wd[k*3+0], s0); s1 = fmaf(hv, Wd[k*3+1], s1); s2 = fmaf(hv, Wd[k*3+2], s2);
    }
    buf[0][tid] = s0; buf[1][tid] = s1; buf[2][tid] = s2;
    __syncthreads();
    for (int s = 64; s > 0; s >>= 1) {
        if (tid < s) { buf[0][tid]+=buf[0][tid+s]; buf[1][tid]+=buf[1][tid+s]; buf[2][tid]+=buf[2][tid+s]; }
        __syncthreads();
    }
    if (tid < 3) out[b*3 + tid] = fmaxf(buf[tid][0] + bd[tid], 0.f);
}

// ------------- pipelined HMMA GEMM + optional fused LSTM gate epilogue -----
// D[128,128] = A[128,K] @ B[128,K]^T  (both K-major, hi/lo split, 3 MMA terms)
// 4 warps, 64x64 warp tile (4x4 fragments): mma:ldsm issue ratio 3:1.
// mode 0: Z[row,n] = D.   mode 1: z = D + Z + bias -> gates -> c,h(split bf16).
__global__ void __launch_bounds__(128, 1)
lstm_gemm(const __nv_bfloat16* __restrict__ Ah, const __nv_bfloat16* __restrict__ Al,
          const __nv_bfloat16* __restrict__ Bh, const __nv_bfloat16* __restrict__ Bl,
          int K, float* __restrict__ Z, int mode,
          const float* __restrict__ biasI, float* __restrict__ cst,
          __nv_bfloat16* __restrict__ hh, __nv_bfloat16* __restrict__ hl,
          const int* __restrict__ seqlen, float* __restrict__ hidden, int t)
{
    extern __shared__ char smem[];
    const int tid = threadIdx.x, wid = tid >> 5;
    const int wr = wid & 1, wc = wid >> 1;          // 2x2 warp grid, 64x64 tiles
    const int bx = blockIdx.x, by = blockIdx.y;
    const int nch = K >> 5;
    const uint32_t sbase = smem_u32(smem);

    const __nv_bfloat16* srcs[4] = {Ah, Al, Bh, Bl};
    const int rb[4] = {by*128, by*128, bx*128, bx*128};

    auto load_chunk = [&](int ch, int buf) {
        if (ch < nch) {
            const int k0 = ch << 5;
            const uint32_t st = sbase + (uint32_t)buf * STG;
            #pragma unroll
            for (int op = 0; op < 4; op++) {
                const __nv_bfloat16* src = srcs[op] + (size_t)rb[op] * K + k0;
                const uint32_t sb = st + op * OPB;
                #pragma unroll
                for (int it = 0; it < 4; it++) {
                    int ck = it * 128 + tid;        // 0..511
                    int r = ck >> 2, c = ck & 3;
                    cp16(sb + r * 80 + c * 16, src + (size_t)r * K + c * 8);
                }
            }
        }
        cp_commit();                                 // empty commit keeps group count aligned
    };

    wmma::fragment<wmma::accumulator, 16, 16, 16, float> acc[4][4];
    #pragma unroll
    for (int m = 0; m < 4; m++)
        #pragma unroll
        for (int n = 0; n < 4; n++) wmma::fill_fragment(acc[m][n], 0.f);

    load_chunk(0, 0); load_chunk(1, 1); load_chunk(2, 2); load_chunk(3, 3);

    for (int i = 0; i < nch; i++) {
        cp_wait3();                                  // stage i resident
        __syncthreads();
        load_chunk(i + 4, (i + 4) % NSTAGE);
        const __nv_bfloat16* sb = (const __nv_bfloat16*)(smem + (size_t)(i % NSTAGE) * STG);
        const __nv_bfloat16* sAh_ = sb;
        const __nv_bfloat16* sAl_ = sb + OPE;
        const __nv_bfloat16* sBh_ = sb + 2 * OPE;
        const __nv_bfloat16* sBl_ = sb + 3 * OPE;
        #pragma unroll
        for (int kk = 0; kk < 2; kk++) {
            wmma::fragment<wmma::matrix_a, 16, 16, 16, __nv_bfloat16, wmma::row_major> fah[4], fal[4];
            wmma::fragment<wmma::matrix_b, 16, 16, 16, __nv_bfloat16, wmma::col_major> fbh[4], fbl[4];
            #pragma unroll
            for (int m = 0; m < 4; m++) {
                wmma::load_matrix_sync(fah[m], sAh_ + (wr*64 + m*16)*40 + kk*16, 40);
                wmma::load_matrix_sync(fal[m], sAl_ + (wr*64 + m*16)*40 + kk*16, 40);
            }
            #pragma unroll
            for (int n = 0; n < 4; n++) {
                wmma::load_matrix_sync(fbh[n], sBh_ + (wc*64 + n*16)*40 + kk*16, 40);
                wmma::load_matrix_sync(fbl[n], sBl_ + (wc*64 + n*16)*40 + kk*16, 40);
            }
            #pragma unroll
            for (int m = 0; m < 4; m++)
                #pragma unroll
                for (int n = 0; n < 4; n++) {
                    wmma::mma_sync(acc[m][n], fah[m], fbh[n], acc[m][n]);
                    wmma::mma_sync(acc[m][n], fal[m], fbh[n], acc[m][n]);
                    wmma::mma_sync(acc[m][n], fah[m], fbl[n], acc[m][n]);
                }
        }
    }

    if (mode == 0) {
        float* dst = Z + (size_t)(by * 128) * FH + bx * 128;
        #pragma unroll
        for (int m = 0; m < 4; m++)
            #pragma unroll
            for (int n = 0; n < 4; n++)
                wmma::store_matrix_sync(dst + (size_t)(wr*64 + m*16) * FH + wc*64 + n*16,
                                        acc[m][n], FH, wmma::mem_row_major);
        return;
    }

    // ---- fused LSTM gate epilogue ----
    __syncthreads();
    float* Zs = (float*)smem;
    #pragma unroll
    for (int m = 0; m < 4; m++)
        #pragma unroll
        for (int n = 0; n < 4; n++)
            wmma::store_matrix_sync(Zs + (wr*64 + m*16) * LDS_EP + wc*64 + n*16,
                                    acc[m][n], LDS_EP, wmma::mem_row_major);
    __syncthreads();

    const int rl = tid;                              // one row per thread
    const int row = by * 128 + rl;                   // batch index
    const int n0 = bx * 128;                         // interleaved col base
    const int jb = n0 >> 2;                          // j base (32 j's)
    const float* zs = Zs + rl * LDS_EP;
    const float4* zg = (const float4*)(Z + (size_t)row * FH + n0);
    const float4* bi4 = (const float4*)(biasI + n0);
    float* crow = cst + (size_t)row * HH + jb;
    const bool gath = seqlen && (seqlen[row] - 1 == t);

    float cn[32]; __nv_bfloat16 hb[32], lb[32];
    #pragma unroll
    for (int g = 0; g < 32; g++) {
        float4 zv = zg[g], bv = bi4[g];
        float vi = zs[g*4+0] + zv.x + bv.x;
        float vf = zs[g*4+1] + zv.y + bv.y;
        float vg = zs[g*4+2] + zv.z + bv.z;
        float vo = zs[g*4+3] + zv.w + bv.w;
        float ig = 1.f / (1.f + __expf(-vi));
        float fg = 1.f / (1.f + __expf(-vf));
        float gg = tanhf(vg);
        float og = 1.f / (1.f + __expf(-vo));
        float c_ = fg * crow[g] + ig * gg;
        cn[g] = c_;
        float hv = og * tanhf(c_);
        __nv_bfloat16 hi_ = __float2bfloat16(hv);
        hb[g] = hi_;
        lb[g] = __float2bfloat16(hv - __bfloat162float(hi_));
        if (gath) hidden[(size_t)row * HH + jb + g] = hv;
    }
    #pragma unroll
    for (int q = 0; q < 8; q++)
        ((float4*)crow)[q] = make_float4(cn[q*4], cn[q*4+1], cn[q*4+2], cn[q*4+3]);
    #pragma unroll
    for (int q = 0; q < 4; q++) {
        *(uint4*)(hh + (size_t)row * HH + jb + q*8) = ((uint4*)hb)[q];
        *(uint4*)(hl + (size_t)row * HH + jb + q*8) = ((uint4*)lb)[q];
    }
}

// ------------- launch -------------
extern "C" void kernel_launch(void* const* d_in, const int* in_sizes, int n_in,
                              void* d_out, int out_size)
{
    const float* chars  = (const float*)d_in[0];
    const int*   seqlen = (const int*)  d_in[1];
    const float* W1 = (const float*)d_in[2];
    const float* U1 = (const float*)d_in[3];
    const float* b1 = (const float*)d_in[4];
    const float* W2 = (const float*)d_in[5];
    const float* U2 = (const float*)d_in[6];
    const float* b2 = (const float*)d_in[7];
    const float* Wd = (const float*)d_in[8];
    const float* bd = (const float*)d_in[9];
    float* out = (float*)d_out;

    cudaFuncSetAttribute(lstm_gemm, cudaFuncAttributeMaxDynamicSharedMemorySize, SMEM_DYN);

    float *Z, *c1, *c2, *hidden, *b1i, *b2i;
    __nv_bfloat16 *Xh, *Xl, *H1h, *H1l, *H2h, *H2l;
    __nv_bfloat16 *W1h, *W1l, *U1h, *U1l, *W2h, *W2l, *U2h, *U2l;
    cudaGetSymbolAddress((void**)&Z, d_Z);
    cudaGetSymbolAddress((void**)&c1, d_c1);   cudaGetSymbolAddress((void**)&c2, d_c2);
    cudaGetSymbolAddress((void**)&hidden, d_hidden);
    cudaGetSymbolAddress((void**)&b1i, d_b1i); cudaGetSymbolAddress((void**)&b2i, d_b2i);
    cudaGetSymbolAddress((void**)&Xh, d_Xh);   cudaGetSymbolAddress((void**)&Xl, d_Xl);
    cudaGetSymbolAddress((void**)&H1h, d_H1h); cudaGetSymbolAddress((void**)&H1l, d_H1l);
    cudaGetSymbolAddress((void**)&H2h, d_H2h); cudaGetSymbolAddress((void**)&H2l, d_H2l);
    cudaGetSymbolAddress((void**)&W1h, d_W1h); cudaGetSymbolAddress((void**)&W1l, d_W1l);
    cudaGetSymbolAddress((void**)&U1h, d_U1h); cudaGetSymbolAddress((void**)&U1l, d_U1l);
    cudaGetSymbolAddress((void**)&W2h, d_W2h); cudaGetSymbolAddress((void**)&W2l, d_W2l);
    cudaGetSymbolAddress((void**)&U2h, d_U2h); cudaGetSymbolAddress((void**)&U2l, d_U2l);

    split_w<<<(FH*DIN)/256, 256>>>(W1, W1h, W1l, DIN);
    split_w<<<(FH*HH)/256, 256>>>(U1, U1h, U1l, HH);
    split_w<<<(FH*HH)/256, 256>>>(W2, W2h, W2l, HH);
    split_w<<<(FH*HH)/256, 256>>>(U2, U2h, U2l, HH);
    interleave_bias<<<FH/256, 256>>>(b1, b1i);
    interleave_bias<<<FH/256, 256>>>(b2, b2i);
    split_chars<<<(TBROWS*64)/256, 256>>>(chars, Xh, Xl);
    init_states<<<(BB*HH)/256, 256>>>();

    const size_t HB = (size_t)BB * HH;
    dim3 gBig(FH/128, TBROWS/128);   // (32, 512)
    dim3 gStep(FH/128, BB/128);      // (32, 4)

    // layer 1 input transform: Z = X @ W1t^T
    lstm_gemm<<<gBig, 128, SMEM_DYN>>>(Xh, Xl, W1h, W1l, DIN, Z, 0,
                                       nullptr, nullptr, nullptr, nullptr, nullptr, nullptr, 0);
    // layer 1 recurrence (h_{t-1} = H1 block t, writes block t+1)
    for (int t = 0; t < TT; t++)
        lstm_gemm<<<gStep, 128, SMEM_DYN>>>(H1h + (size_t)t*HB, H1l + (size_t)t*HB,
                                            U1h, U1l, HH, Z + (size_t)t*BB*FH, 1,
                                            b1i, c1, H1h + (size_t)(t+1)*HB, H1l + (size_t)(t+1)*HB,
                                            nullptr, nullptr, t);
    // layer 2 input transform: Z = H1(1..T) @ W2t^T
    lstm_gemm<<<gBig, 128, SMEM_DYN>>>(H1h + HB, H1l + HB, W2h, W2l, HH, Z, 0,
                                       nullptr, nullptr, nullptr, nullptr, nullptr, nullptr, 0);
    // layer 2 recurrence + last-valid gather
    for (int t = 0; t < TT; t++)
        lstm_gemm<<<gStep, 128, SMEM_DYN>>>(H2h + (size_t)t*HB, H2l + (size_t)t*HB,
                                            U2h, U2l, HH, Z + (size_t)t*BB*FH, 1,
                                            b2i, c2, H2h + (size_t)(t+1)*HB, H2l + (size_t)(t+1)*HB,
                                            seqlen, hidden, t);

    dense_relu<<<BB, 128>>>(hidden, Wd, bd, out);
}

// round 9
// speedup vs baseline: 1.5103x; 1.5103x over previous
#include <cuda_runtime.h>
#include <cuda_bf16.h>
#include <mma.h>
#include <cstdint>

using namespace nvcuda;

#define BB   512
#define TT   128
#define DIN  256
#define HH   1024
#define FH   4096
#define TBROWS (TT*BB)

#define BM 64
#define BN 128
#define ABYTES 5120u          // 64 rows * 80 B
#define BBYTES 10240u         // 128 rows * 80 B
#define STG 30720u            // 2*A + 2*B per stage
#define NSTAGE 3
#define SMEM_DYN 92160        // 3 stages
#define LDS_EP 132            // epilogue smem stride (floats)

// ------------- device scratch (no allocation allowed) -------------
__device__ float d_Z[(size_t)TBROWS*FH];
__device__ float d_c1[BB*HH], d_c2[BB*HH];
__device__ float d_hidden[BB*HH];
__device__ float d_b1i[FH], d_b2i[FH];
__device__ int   d_pos[BB], d_orig[BB], d_seqP[BB], d_cnt[TT+1];
__device__ __nv_bfloat16 d_Xh[(size_t)TBROWS*DIN], d_Xl[(size_t)TBROWS*DIN];
__device__ __nv_bfloat16 d_H1h[(size_t)(TT+1)*BB*HH], d_H1l[(size_t)(TT+1)*BB*HH];
__device__ __nv_bfloat16 d_H2h[(size_t)(TT+1)*BB*HH], d_H2l[(size_t)(TT+1)*BB*HH];
__device__ __nv_bfloat16 d_W1h[(size_t)FH*DIN], d_W1l[(size_t)FH*DIN];
__device__ __nv_bfloat16 d_U1h[(size_t)FH*HH],  d_U1l[(size_t)FH*HH];
__device__ __nv_bfloat16 d_W2h[(size_t)FH*HH],  d_W2l[(size_t)FH*HH];
__device__ __nv_bfloat16 d_U2h[(size_t)FH*HH],  d_U2l[(size_t)FH*HH];

// ------------- PTX helpers (Ampere-level: valid on plain sm_103) ------
__device__ __forceinline__ uint32_t smem_u32(const void* p) {
    uint32_t a;
    asm("{ .reg .u64 t; cvta.to.shared.u64 t, %1; cvt.u32.u64 %0, t; }" : "=r"(a) : "l"(p));
    return a;
}
__device__ __forceinline__ void cp16(uint32_t d, const void* s) {
    asm volatile("cp.async.cg.shared.global [%0], [%1], 16;" :: "r"(d), "l"(s) : "memory");
}
__device__ __forceinline__ void cp_commit() { asm volatile("cp.async.commit_group;" ::: "memory"); }
__device__ __forceinline__ void cp_wait1()  { asm volatile("cp.async.wait_group 1;" ::: "memory"); }

// ------------- preprocessing -------------
__global__ void split_w(const float* __restrict__ W, __nv_bfloat16* __restrict__ oh,
                        __nv_bfloat16* __restrict__ ol, int K)
{
    size_t i = (size_t)blockIdx.x * blockDim.x + threadIdx.x;
    int k = (int)(i % K), n = (int)(i / K);
    float x = W[(size_t)k * FH + (n & 3) * HH + (n >> 2)];
    __nv_bfloat16 h = __float2bfloat16(x);
    oh[i] = h;
    ol[i] = __float2bfloat16(x - __bfloat162float(h));
}
__global__ void interleave_bias(const float* __restrict__ b, float* __restrict__ bi)
{
    int n = blockIdx.x * blockDim.x + threadIdx.x;
    bi[n] = b[(n & 3) * HH + (n >> 2)];
}
// deterministic descending-seqlen sort (rank by full scan, no atomics)
__global__ void seq_sort(const int* __restrict__ seqlen)
{
    int b = threadIdx.x;
    int s = seqlen[b];
    int pos = 0;
    for (int j = 0; j < BB; j++) {
        int sj = seqlen[j];
        pos += (sj > s) || (sj == s && j < b);
    }
    d_pos[b] = pos;
    d_orig[pos] = b;
    d_seqP[pos] = s;
}
__global__ void seq_cnt(const int* __restrict__ seqlen)
{
    int t = threadIdx.x;            // 0..128
    if (t > TT) return;
    int c = 0;
    for (int j = 0; j < BB; j++) c += (seqlen[j] >= t + 1);
    d_cnt[t] = c;
}
// chars [B][T][256] -> split bf16 time-major PERMUTED [t*512 + pos[b]][256]
__global__ void split_chars(const float* __restrict__ chars,
                            __nv_bfloat16* __restrict__ xh, __nv_bfloat16* __restrict__ xl)
{
    int idx = blockIdx.x * blockDim.x + threadIdx.x;   // TBROWS*64
    int d4 = idx & 63, rest = idx >> 6;
    int b = rest & (BB - 1), t = rest >> 9;
    float4 v = *(const float4*)(chars + ((size_t)b * TT + t) * DIN + d4 * 4);
    size_t o = ((size_t)t * BB + d_pos[b]) * DIN + d4 * 4;
    float vv[4] = {v.x, v.y, v.z, v.w};
    #pragma unroll
    for (int e = 0; e < 4; e++) {
        __nv_bfloat16 h = __float2bfloat16(vv[e]);
        xh[o + e] = h;
        xl[o + e] = __float2bfloat16(vv[e] - __bfloat162float(h));
    }
}
__global__ void init_states()
{
    int i = blockIdx.x * blockDim.x + threadIdx.x;  // BB*HH
    d_c1[i] = 0.f; d_c2[i] = 0.f;
    __nv_bfloat16 z = __float2bfloat16(0.f);
    d_H1h[i] = z; d_H1l[i] = z; d_H2h[i] = z; d_H2l[i] = z;
}
__global__ void dense_relu(const float* __restrict__ hidden, const float* __restrict__ Wd,
                           const float* __restrict__ bd, float* __restrict__ out)
{
    __shared__ float buf[3][128];
    int b = blockIdx.x, tid = threadIdx.x;
    const float* hb = hidden + (size_t)b * HH;
    float s0 = 0.f, s1 = 0.f, s2 = 0.f;
    for (int k = tid; k < HH; k += 128) {
        float hv = hb[k];
        s0 = fmaf(hv, Wd[k*3+0], s0); s1 = fmaf(hv, Wd[k*3+1], s1); s2 = fmaf(hv, Wd[k*3+2], s2);
    }
    buf[0][tid] = s0; buf[1][tid] = s1; buf[2][tid] = s2;
    __syncthreads();
    for (int s = 64; s > 0; s >>= 1) {
        if (tid < s) { buf[0][tid]+=buf[0][tid+s]; buf[1][tid]+=buf[1][tid+s]; buf[2][tid]+=buf[2][tid+s]; }
        __syncthreads();
    }
    if (tid < 3) out[b*3 + tid] = fmaxf(buf[tid][0] + bd[tid], 0.f);
}

// ------------- pipelined HMMA GEMM (M=64) + activity skip + fused gates ----
// D[64,128] = A[64,K] @ B[128,K]^T (K-major, hi/lo split, 3 MMA terms)
// mode 0: Z[row,n] = D (skip tiles with no active row at their timestep)
// mode 1: z = D + Z + bias -> gates -> c,h(split bf16) (skip if tile >= cnt[step])
__global__ void __launch_bounds__(128, 2)
lstm_gemm(const __nv_bfloat16* __restrict__ Ah, const __nv_bfloat16* __restrict__ Al,
          const __nv_bfloat16* __restrict__ Bh, const __nv_bfloat16* __restrict__ Bl,
          int K, float* __restrict__ Z, int mode,
          const float* __restrict__ biasI, float* __restrict__ cst,
          __nv_bfloat16* __restrict__ hh, __nv_bfloat16* __restrict__ hl,
          float* __restrict__ hidden, int step)
{
    const int bx = blockIdx.x, by = blockIdx.y;
    // ---- activity skip ----
    if (mode == 0) {
        int row0 = by * BM;
        int tt = row0 >> 9, p0 = row0 & 511;
        if (p0 >= d_cnt[tt]) return;
    } else {
        if (by * BM >= d_cnt[step]) return;
    }

    extern __shared__ char smem[];
    const int tid = threadIdx.x, wid = tid >> 5;
    const int wr = wid & 1, wc = wid >> 1;           // 2x2 warps, 32x64 warp tile
    const int nch = K >> 5;
    const uint32_t sbase = smem_u32(smem);

    const int rbA = by * BM, rbB = bx * BN;

    auto load_chunk = [&](int ch, int buf) {
        if (ch < nch) {
            const int k0 = ch << 5;
            const uint32_t st = sbase + (uint32_t)buf * STG;
            const __nv_bfloat16* sa[2] = {Ah, Al};
            const __nv_bfloat16* sbp[2] = {Bh, Bl};
            #pragma unroll
            for (int op = 0; op < 2; op++) {
                const __nv_bfloat16* src = sa[op] + (size_t)rbA * K + k0;
                uint32_t sb = st + op * ABYTES;
                #pragma unroll
                for (int it = 0; it < 2; it++) {
                    int ck = it * 128 + tid;         // 0..255
                    int r = ck >> 2, c = ck & 3;
                    cp16(sb + r * 80 + c * 16, src + (size_t)r * K + c * 8);
                }
            }
            #pragma unroll
            for (int op = 0; op < 2; op++) {
                const __nv_bfloat16* src = sbp[op] + (size_t)rbB * K + k0;
                uint32_t sb = st + 2 * ABYTES + op * BBYTES;
                #pragma unroll
                for (int it = 0; it < 4; it++) {
                    int ck = it * 128 + tid;         // 0..511
                    int r = ck >> 2, c = ck & 3;
                    cp16(sb + r * 80 + c * 16, src + (size_t)r * K + c * 8);
                }
            }
        }
        cp_commit();
    };

    wmma::fragment<wmma::accumulator, 16, 16, 16, float> acc[2][4];
    #pragma unroll
    for (int m = 0; m < 2; m++)
        #pragma unroll
        for (int n = 0; n < 4; n++) wmma::fill_fragment(acc[m][n], 0.f);

    load_chunk(0, 0); load_chunk(1, 1);

    for (int i = 0; i < nch; i++) {
        cp_wait1();
        __syncthreads();
        load_chunk(i + 2, (i + 2) % NSTAGE);
        const __nv_bfloat16* sb = (const __nv_bfloat16*)(smem + (size_t)(i % NSTAGE) * STG);
        const __nv_bfloat16* sAh_ = sb;
        const __nv_bfloat16* sAl_ = sb + 2560;
        const __nv_bfloat16* sBh_ = sb + 5120;
        const __nv_bfloat16* sBl_ = sb + 10240;
        #pragma unroll
        for (int kk = 0; kk < 2; kk++) {
            wmma::fragment<wmma::matrix_a, 16, 16, 16, __nv_bfloat16, wmma::row_major> fah[2], fal[2];
            wmma::fragment<wmma::matrix_b, 16, 16, 16, __nv_bfloat16, wmma::col_major> fbh[4], fbl[4];
            #pragma unroll
            for (int m = 0; m < 2; m++) {
                wmma::load_matrix_sync(fah[m], sAh_ + (wr*32 + m*16)*40 + kk*16, 40);
                wmma::load_matrix_sync(fal[m], sAl_ + (wr*32 + m*16)*40 + kk*16, 40);
            }
            #pragma unroll
            for (int n = 0; n < 4; n++) {
                wmma::load_matrix_sync(fbh[n], sBh_ + (wc*64 + n*16)*40 + kk*16, 40);
                wmma::load_matrix_sync(fbl[n], sBl_ + (wc*64 + n*16)*40 + kk*16, 40);
            }
            #pragma unroll
            for (int m = 0; m < 2; m++)
                #pragma unroll
                for (int n = 0; n < 4; n++) {
                    wmma::mma_sync(acc[m][n], fah[m], fbh[n], acc[m][n]);
                    wmma::mma_sync(acc[m][n], fal[m], fbh[n], acc[m][n]);
                    wmma::mma_sync(acc[m][n], fah[m], fbl[n], acc[m][n]);
                }
        }
    }

    if (mode == 0) {
        float* dst = Z + (size_t)rbA * FH + rbB;
        #pragma unroll
        for (int m = 0; m < 2; m++)
            #pragma unroll
            for (int n = 0; n < 4; n++)
                wmma::store_matrix_sync(dst + (size_t)(wr*32 + m*16) * FH + wc*64 + n*16,
                                        acc[m][n], FH, wmma::mem_row_major);
        return;
    }

    // ---- fused LSTM gate epilogue (64 rows) ----
    __syncthreads();
    float* Zs = (float*)smem;
    #pragma unroll
    for (int m = 0; m < 2; m++)
        #pragma unroll
        for (int n = 0; n < 4; n++)
            wmma::store_matrix_sync(Zs + (wr*32 + m*16) * LDS_EP + wc*64 + n*16,
                                    acc[m][n], LDS_EP, wmma::mem_row_major);
    __syncthreads();

    const int rl = tid >> 1, half = tid & 1;
    const int p = by * BM + rl;                      // permuted batch index
    const int n0 = bx * BN + half * 64;
    const int jb = n0 >> 2;                          // 16 j's per thread
    const float* zs = Zs + rl * LDS_EP + half * 64;
    const float4* zg = (const float4*)(Z + (size_t)p * FH + n0);
    const float4* bi4 = (const float4*)(biasI + n0);
    float* crow = cst + (size_t)p * HH + jb;
    // FIX vs R8: null-guard hidden (layer-1 calls pass nullptr; unguarded
    // gather wrote through nullptr -> illegal memory access)
    const bool gath = (hidden != nullptr) && (d_seqP[p] - 1 == step);
    float* hidrow = gath ? (hidden + (size_t)d_orig[p] * HH + jb) : nullptr;

    float cn[16]; __nv_bfloat16 hb[16], lb[16];
    #pragma unroll
    for (int g = 0; g < 16; g++) {
        float4 zv = zg[g], bv = bi4[g];
        float vi = zs[g*4+0] + zv.x + bv.x;
        float vf = zs[g*4+1] + zv.y + bv.y;
        float vg = zs[g*4+2] + zv.z + bv.z;
        float vo = zs[g*4+3] + zv.w + bv.w;
        float ig = 1.f / (1.f + __expf(-vi));
        float fg = 1.f / (1.f + __expf(-vf));
        float gg = tanhf(vg);
        float og = 1.f / (1.f + __expf(-vo));
        float c_ = fg * crow[g] + ig * gg;
        cn[g] = c_;
        float hv = og * tanhf(c_);
        __nv_bfloat16 hi_ = __float2bfloat16(hv);
        hb[g] = hi_;
        lb[g] = __float2bfloat16(hv - __bfloat162float(hi_));
        if (gath) hidrow[g] = hv;
    }
    #pragma unroll
    for (int q = 0; q < 4; q++)
        ((float4*)crow)[q] = make_float4(cn[q*4], cn[q*4+1], cn[q*4+2], cn[q*4+3]);
    *(uint4*)(hh + (size_t)p * HH + jb)     = ((uint4*)hb)[0];
    *(uint4*)(hh + (size_t)p * HH + jb + 8) = ((uint4*)hb)[1];
    *(uint4*)(hl + (size_t)p * HH + jb)     = ((uint4*)lb)[0];
    *(uint4*)(hl + (size_t)p * HH + jb + 8) = ((uint4*)lb)[1];
}

// ------------- launch -------------
extern "C" void kernel_launch(void* const* d_in, const int* in_sizes, int n_in,
                              void* d_out, int out_size)
{
    const float* chars  = (const float*)d_in[0];
    const int*   seqlen = (const int*)  d_in[1];
    const float* W1 = (const float*)d_in[2];
    const float* U1 = (const float*)d_in[3];
    const float* b1 = (const float*)d_in[4];
    const float* W2 = (const float*)d_in[5];
    const float* U2 = (const float*)d_in[6];
    const float* b2 = (const float*)d_in[7];
    const float* Wd = (const float*)d_in[8];
    const float* bd = (const float*)d_in[9];
    float* out = (float*)d_out;

    cudaFuncSetAttribute(lstm_gemm, cudaFuncAttributeMaxDynamicSharedMemorySize, SMEM_DYN);

    float *Z, *c1, *c2, *hidden, *b1i, *b2i;
    __nv_bfloat16 *Xh, *Xl, *H1h, *H1l, *H2h, *H2l;
    __nv_bfloat16 *W1h, *W1l, *U1h, *U1l, *W2h, *W2l, *U2h, *U2l;
    cudaGetSymbolAddress((void**)&Z, d_Z);
    cudaGetSymbolAddress((void**)&c1, d_c1);   cudaGetSymbolAddress((void**)&c2, d_c2);
    cudaGetSymbolAddress((void**)&hidden, d_hidden);
    cudaGetSymbolAddress((void**)&b1i, d_b1i); cudaGetSymbolAddress((void**)&b2i, d_b2i);
    cudaGetSymbolAddress((void**)&Xh, d_Xh);   cudaGetSymbolAddress((void**)&Xl, d_Xl);
    cudaGetSymbolAddress((void**)&H1h, d_H1h); cudaGetSymbolAddress((void**)&H1l, d_H1l);
    cudaGetSymbolAddress((void**)&H2h, d_H2h); cudaGetSymbolAddress((void**)&H2l, d_H2l);
    cudaGetSymbolAddress((void**)&W1h, d_W1h); cudaGetSymbolAddress((void**)&W1l, d_W1l);
    cudaGetSymbolAddress((void**)&U1h, d_U1h); cudaGetSymbolAddress((void**)&U1l, d_U1l);
    cudaGetSymbolAddress((void**)&W2h, d_W2h); cudaGetSymbolAddress((void**)&W2l, d_W2l);
    cudaGetSymbolAddress((void**)&U2h, d_U2h); cudaGetSymbolAddress((void**)&U2l, d_U2l);

    split_w<<<(FH*DIN)/256, 256>>>(W1, W1h, W1l, DIN);
    split_w<<<(FH*HH)/256, 256>>>(U1, U1h, U1l, HH);
    split_w<<<(FH*HH)/256, 256>>>(W2, W2h, W2l, HH);
    split_w<<<(FH*HH)/256, 256>>>(U2, U2h, U2l, HH);
    interleave_bias<<<FH/256, 256>>>(b1, b1i);
    interleave_bias<<<FH/256, 256>>>(b2, b2i);
    seq_sort<<<1, BB>>>(seqlen);
    seq_cnt<<<1, TT+1>>>(seqlen);
    split_chars<<<(TBROWS*64)/256, 256>>>(chars, Xh, Xl);
    init_states<<<(BB*HH)/256, 256>>>();

    const size_t HB = (size_t)BB * HH;
    dim3 gBig(FH/BN, TBROWS/BM);   // (32, 1024)
    dim3 gStep(FH/BN, BB/BM);      // (32, 8)

    // layer 1 input transform: Z = X @ W1t^T (tiles skipped past cnt[t])
    lstm_gemm<<<gBig, 128, SMEM_DYN>>>(Xh, Xl, W1h, W1l, DIN, Z, 0,
                                       nullptr, nullptr, nullptr, nullptr, nullptr, 0);
    // layer 1 recurrence
    for (int t = 0; t < TT; t++)
        lstm_gemm<<<gStep, 128, SMEM_DYN>>>(H1h + (size_t)t*HB, H1l + (size_t)t*HB,
                                            U1h, U1l, HH, Z + (size_t)t*BB*FH, 1,
                                            b1i, c1, H1h + (size_t)(t+1)*HB, H1l + (size_t)(t+1)*HB,
                                            nullptr, t);
    // layer 2 input transform: Z = H1(1..T) @ W2t^T
    lstm_gemm<<<gBig, 128, SMEM_DYN>>>(H1h + HB, H1l + HB, W2h, W2l, HH, Z, 0,
                                       nullptr, nullptr, nullptr, nullptr, nullptr, 0);
    // layer 2 recurrence + last-valid gather (scattered to original batch order)
    for (int t = 0; t < TT; t++)
        lstm_gemm<<<gStep, 128, SMEM_DYN>>>(H2h + (size_t)t*HB, H2l + (size_t)t*HB,
                                            U2h, U2l, HH, Z + (size_t)t*BB*FH, 1,
                                            b2i, c2, H2h + (size_t)(t+1)*HB, H2l + (size_t)(t+1)*HB,
                                            hidden, t);

    dense_relu<<<BB, 128>>>(hidden, Wd, bd, out);
}

// round 10
// speedup vs baseline: 1.9772x; 1.3092x over previous
#include <cuda_runtime.h>
#include <cuda_bf16.h>
#include <mma.h>
#include <cstdint>

using namespace nvcuda;

#define BB   512
#define TT   128
#define DIN  256
#define HH   1024
#define FH   4096
#define TBROWS (TT*BB)

#define BM 64
#define BN 128
#define ABYTES 5120u          // 64 rows * 80 B
#define BBYTES 10240u         // 128 rows * 80 B
#define STG 30720u            // 2*A + 2*B per stage
#define NSTAGE 3
#define SMEM_DYN 92160        // 3 stages
#define LDS_EP 132            // epilogue smem stride (floats)

// ------------- device scratch (no allocation allowed) -------------
__device__ float d_Z1[(size_t)TBROWS*FH];
__device__ float d_Z2[(size_t)TBROWS*FH];
__device__ float d_c1[BB*HH], d_c2[BB*HH];
__device__ float d_hidden[BB*HH];
__device__ float d_b1i[FH], d_b2i[FH];
__device__ int   d_pos[BB], d_orig[BB], d_seqP[BB], d_cnt[TT+1];
__device__ __nv_bfloat16 d_Xh[(size_t)TBROWS*DIN], d_Xl[(size_t)TBROWS*DIN];
__device__ __nv_bfloat16 d_H1h[(size_t)(TT+1)*BB*HH], d_H1l[(size_t)(TT+1)*BB*HH];
__device__ __nv_bfloat16 d_H2h[(size_t)(TT+1)*BB*HH], d_H2l[(size_t)(TT+1)*BB*HH];
__device__ __nv_bfloat16 d_W1h[(size_t)FH*DIN], d_W1l[(size_t)FH*DIN];
__device__ __nv_bfloat16 d_U1h[(size_t)FH*HH],  d_U1l[(size_t)FH*HH];
__device__ __nv_bfloat16 d_W2h[(size_t)FH*HH],  d_W2l[(size_t)FH*HH];
__device__ __nv_bfloat16 d_U2h[(size_t)FH*HH],  d_U2l[(size_t)FH*HH];

// ------------- PTX helpers (Ampere-level: valid on plain sm_103) ------
__device__ __forceinline__ uint32_t smem_u32(const void* p) {
    uint32_t a;
    asm("{ .reg .u64 t; cvta.to.shared.u64 t, %1; cvt.u32.u64 %0, t; }" : "=r"(a) : "l"(p));
    return a;
}
__device__ __forceinline__ void cp16(uint32_t d, const void* s) {
    asm volatile("cp.async.cg.shared.global [%0], [%1], 16;" :: "r"(d), "l"(s) : "memory");
}
__device__ __forceinline__ void cp_commit() { asm volatile("cp.async.commit_group;" ::: "memory"); }
__device__ __forceinline__ void cp_wait1()  { asm volatile("cp.async.wait_group 1;" ::: "memory"); }

// ------------- preprocessing -------------
__global__ void split_w(const float* __restrict__ W, __nv_bfloat16* __restrict__ oh,
                        __nv_bfloat16* __restrict__ ol, int K)
{
    size_t i = (size_t)blockIdx.x * blockDim.x + threadIdx.x;
    int k = (int)(i % K), n = (int)(i / K);
    float x = W[(size_t)k * FH + (n & 3) * HH + (n >> 2)];
    __nv_bfloat16 h = __float2bfloat16(x);
    oh[i] = h;
    ol[i] = __float2bfloat16(x - __bfloat162float(h));
}
__global__ void interleave_bias(const float* __restrict__ b, float* __restrict__ bi)
{
    int n = blockIdx.x * blockDim.x + threadIdx.x;
    bi[n] = b[(n & 3) * HH + (n >> 2)];
}
// deterministic descending-seqlen sort (rank by full scan, no atomics)
__global__ void seq_sort(const int* __restrict__ seqlen)
{
    int b = threadIdx.x;
    int s = seqlen[b];
    int pos = 0;
    for (int j = 0; j < BB; j++) {
        int sj = seqlen[j];
        pos += (sj > s) || (sj == s && j < b);
    }
    d_pos[b] = pos;
    d_orig[pos] = b;
    d_seqP[pos] = s;
}
__global__ void seq_cnt(const int* __restrict__ seqlen)
{
    int t = threadIdx.x;            // 0..128
    if (t > TT) return;
    int c = 0;
    for (int j = 0; j < BB; j++) c += (seqlen[j] >= t + 1);
    d_cnt[t] = c;
}
// chars [B][T][256] -> split bf16 time-major PERMUTED [t*512 + pos[b]][256]
__global__ void split_chars(const float* __restrict__ chars,
                            __nv_bfloat16* __restrict__ xh, __nv_bfloat16* __restrict__ xl)
{
    int idx = blockIdx.x * blockDim.x + threadIdx.x;   // TBROWS*64
    int d4 = idx & 63, rest = idx >> 6;
    int b = rest & (BB - 1), t = rest >> 9;
    float4 v = *(const float4*)(chars + ((size_t)b * TT + t) * DIN + d4 * 4);
    size_t o = ((size_t)t * BB + d_pos[b]) * DIN + d4 * 4;
    float vv[4] = {v.x, v.y, v.z, v.w};
    #pragma unroll
    for (int e = 0; e < 4; e++) {
        __nv_bfloat16 h = __float2bfloat16(vv[e]);
        xh[o + e] = h;
        xl[o + e] = __float2bfloat16(vv[e] - __bfloat162float(h));
    }
}
__global__ void init_states()
{
    int i = blockIdx.x * blockDim.x + threadIdx.x;  // BB*HH
    d_c1[i] = 0.f; d_c2[i] = 0.f;
    __nv_bfloat16 z = __float2bfloat16(0.f);
    d_H1h[i] = z; d_H1l[i] = z; d_H2h[i] = z; d_H2l[i] = z;
}
__global__ void dense_relu(const float* __restrict__ hidden, const float* __restrict__ Wd,
                           const float* __restrict__ bd, float* __restrict__ out)
{
    __shared__ float buf[3][128];
    int b = blockIdx.x, tid = threadIdx.x;
    const float* hb = hidden + (size_t)b * HH;
    float s0 = 0.f, s1 = 0.f, s2 = 0.f;
    for (int k = tid; k < HH; k += 128) {
        float hv = hb[k];
        s0 = fmaf(hv, Wd[k*3+0], s0); s1 = fmaf(hv, Wd[k*3+1], s1); s2 = fmaf(hv, Wd[k*3+2], s2);
    }
    buf[0][tid] = s0; buf[1][tid] = s1; buf[2][tid] = s2;
    __syncthreads();
    for (int s = 64; s > 0; s >>= 1) {
        if (tid < s) { buf[0][tid]+=buf[0][tid+s]; buf[1][tid]+=buf[1][tid+s]; buf[2][tid]+=buf[2][tid+s]; }
        __syncthreads();
    }
    if (tid < 3) out[b*3 + tid] = fmaxf(buf[tid][0] + bd[tid], 0.f);
}

// ------------- GEMM core (shared by big-GEMM and tick kernels) -------------
// D[64,128] = A[64,K] @ B[128,K]^T (K-major, hi/lo split, 3 MMA terms)
// mode 0: Z[rowA,n] = D.  mode 1: z = D + Z + bias -> gates -> c,h(split bf16).
__device__ __forceinline__ void gemm_core(
    const __nv_bfloat16* __restrict__ Ah, const __nv_bfloat16* __restrict__ Al,
    const __nv_bfloat16* __restrict__ Bh, const __nv_bfloat16* __restrict__ Bl,
    int K, float* __restrict__ Z, int mode,
    const float* __restrict__ biasI, float* __restrict__ cst,
    __nv_bfloat16* __restrict__ hh, __nv_bfloat16* __restrict__ hl,
    float* __restrict__ hidden, int step, int rbA, int rbB, char* smem)
{
    const int tid = threadIdx.x, wid = tid >> 5;
    const int wr = wid & 1, wc = wid >> 1;           // 2x2 warps, 32x64 warp tile
    const int nch = K >> 5;
    const uint32_t sbase = smem_u32(smem);

    auto load_chunk = [&](int ch, int buf) {
        if (ch < nch) {
            const int k0 = ch << 5;
            const uint32_t st = sbase + (uint32_t)buf * STG;
            const __nv_bfloat16* sa[2] = {Ah, Al};
            const __nv_bfloat16* sbp[2] = {Bh, Bl};
            #pragma unroll
            for (int op = 0; op < 2; op++) {
                const __nv_bfloat16* src = sa[op] + (size_t)rbA * K + k0;
                uint32_t sb = st + op * ABYTES;
                #pragma unroll
                for (int it = 0; it < 2; it++) {
                    int ck = it * 128 + tid;         // 0..255
                    int r = ck >> 2, c = ck & 3;
                    cp16(sb + r * 80 + c * 16, src + (size_t)r * K + c * 8);
                }
            }
            #pragma unroll
            for (int op = 0; op < 2; op++) {
                const __nv_bfloat16* src = sbp[op] + (size_t)rbB * K + k0;
                uint32_t sb = st + 2 * ABYTES + op * BBYTES;
                #pragma unroll
                for (int it = 0; it < 4; it++) {
                    int ck = it * 128 + tid;         // 0..511
                    int r = ck >> 2, c = ck & 3;
                    cp16(sb + r * 80 + c * 16, src + (size_t)r * K + c * 8);
                }
            }
        }
        cp_commit();
    };

    wmma::fragment<wmma::accumulator, 16, 16, 16, float> acc[2][4];
    #pragma unroll
    for (int m = 0; m < 2; m++)
        #pragma unroll
        for (int n = 0; n < 4; n++) wmma::fill_fragment(acc[m][n], 0.f);

    load_chunk(0, 0); load_chunk(1, 1);

    for (int i = 0; i < nch; i++) {
        cp_wait1();
        __syncthreads();
        load_chunk(i + 2, (i + 2) % NSTAGE);
        const __nv_bfloat16* sb = (const __nv_bfloat16*)(smem + (size_t)(i % NSTAGE) * STG);
        const __nv_bfloat16* sAh_ = sb;
        const __nv_bfloat16* sAl_ = sb + 2560;
        const __nv_bfloat16* sBh_ = sb + 5120;
        const __nv_bfloat16* sBl_ = sb + 10240;
        #pragma unroll
        for (int kk = 0; kk < 2; kk++) {
            wmma::fragment<wmma::matrix_a, 16, 16, 16, __nv_bfloat16, wmma::row_major> fah[2], fal[2];
            wmma::fragment<wmma::matrix_b, 16, 16, 16, __nv_bfloat16, wmma::col_major> fbh[4], fbl[4];
            #pragma unroll
            for (int m = 0; m < 2; m++) {
                wmma::load_matrix_sync(fah[m], sAh_ + (wr*32 + m*16)*40 + kk*16, 40);
                wmma::load_matrix_sync(fal[m], sAl_ + (wr*32 + m*16)*40 + kk*16, 40);
            }
            #pragma unroll
            for (int n = 0; n < 4; n++) {
                wmma::load_matrix_sync(fbh[n], sBh_ + (wc*64 + n*16)*40 + kk*16, 40);
                wmma::load_matrix_sync(fbl[n], sBl_ + (wc*64 + n*16)*40 + kk*16, 40);
            }
            #pragma unroll
            for (int m = 0; m < 2; m++)
                #pragma unroll
                for (int n = 0; n < 4; n++) {
                    wmma::mma_sync(acc[m][n], fah[m], fbh[n], acc[m][n]);
                    wmma::mma_sync(acc[m][n], fal[m], fbh[n], acc[m][n]);
                    wmma::mma_sync(acc[m][n], fah[m], fbl[n], acc[m][n]);
                }
        }
    }

    if (mode == 0) {
        float* dst = Z + (size_t)rbA * FH + rbB;
        #pragma unroll
        for (int m = 0; m < 2; m++)
            #pragma unroll
            for (int n = 0; n < 4; n++)
                wmma::store_matrix_sync(dst + (size_t)(wr*32 + m*16) * FH + wc*64 + n*16,
                                        acc[m][n], FH, wmma::mem_row_major);
        return;
    }

    // ---- fused LSTM gate epilogue (64 rows) ----
    __syncthreads();
    float* Zs = (float*)smem;
    #pragma unroll
    for (int m = 0; m < 2; m++)
        #pragma unroll
        for (int n = 0; n < 4; n++)
            wmma::store_matrix_sync(Zs + (wr*32 + m*16) * LDS_EP + wc*64 + n*16,
                                    acc[m][n], LDS_EP, wmma::mem_row_major);
    __syncthreads();

    const int rl = tid >> 1, half = tid & 1;
    const int p = rbA + rl;                          // permuted batch index
    const int n0 = rbB + half * 64;
    const int jb = n0 >> 2;                          // 16 j's per thread
    const float* zs = Zs + rl * LDS_EP + half * 64;
    const float4* zg = (const float4*)(Z + (size_t)p * FH + n0);
    const float4* bi4 = (const float4*)(biasI + n0);
    float* crow = cst + (size_t)p * HH + jb;
    const bool gath = (hidden != nullptr) && (d_seqP[p] - 1 == step);
    float* hidrow = gath ? (hidden + (size_t)d_orig[p] * HH + jb) : nullptr;

    float cn[16]; __nv_bfloat16 hb[16], lb[16];
    #pragma unroll
    for (int g = 0; g < 16; g++) {
        float4 zv = zg[g], bv = bi4[g];
        float vi = zs[g*4+0] + zv.x + bv.x;
        float vf = zs[g*4+1] + zv.y + bv.y;
        float vg = zs[g*4+2] + zv.z + bv.z;
        float vo = zs[g*4+3] + zv.w + bv.w;
        float ig = 1.f / (1.f + __expf(-vi));
        float fg = 1.f / (1.f + __expf(-vf));
        float gg = tanhf(vg);
        float og = 1.f / (1.f + __expf(-vo));
        float c_ = fg * crow[g] + ig * gg;
        cn[g] = c_;
        float hv = og * tanhf(c_);
        __nv_bfloat16 hi_ = __float2bfloat16(hv);
        hb[g] = hi_;
        lb[g] = __float2bfloat16(hv - __bfloat162float(hi_));
        if (gath) hidrow[g] = hv;
    }
    #pragma unroll
    for (int q = 0; q < 4; q++)
        ((float4*)crow)[q] = make_float4(cn[q*4], cn[q*4+1], cn[q*4+2], cn[q*4+3]);
    *(uint4*)(hh + (size_t)p * HH + jb)     = ((uint4*)hb)[0];
    *(uint4*)(hh + (size_t)p * HH + jb + 8) = ((uint4*)hb)[1];
    *(uint4*)(hl + (size_t)p * HH + jb)     = ((uint4*)lb)[0];
    *(uint4*)(hl + (size_t)p * HH + jb + 8) = ((uint4*)lb)[1];
}

// big input transform: Z1 = X @ W1t^T over all (t, p) tiles, skip past cnt[t]
__global__ void __launch_bounds__(128, 2)
big_gemm(const __nv_bfloat16* __restrict__ Ah, const __nv_bfloat16* __restrict__ Al,
         const __nv_bfloat16* __restrict__ Bh, const __nv_bfloat16* __restrict__ Bl,
         int K, float* __restrict__ Z)
{
    extern __shared__ char smem[];
    int row0 = blockIdx.y * BM;
    int tt = row0 >> 9, p0 = row0 & 511;
    if (p0 >= d_cnt[tt]) return;
    gemm_core(Ah, Al, Bh, Bl, K, Z, 0, nullptr, nullptr, nullptr, nullptr,
              nullptr, 0, row0, blockIdx.x * BN, smem);
}

// tick kernel: grid (32, 8, 3). z=0: l1 step t; z=1: W2-slice t-1; z=2: l2 step t-2
__global__ void __launch_bounds__(128, 2)
tick_kernel(int t,
            const __nv_bfloat16* __restrict__ U1h, const __nv_bfloat16* __restrict__ U1l,
            const __nv_bfloat16* __restrict__ W2h, const __nv_bfloat16* __restrict__ W2l,
            const __nv_bfloat16* __restrict__ U2h, const __nv_bfloat16* __restrict__ U2l,
            __nv_bfloat16* __restrict__ H1h, __nv_bfloat16* __restrict__ H1l,
            __nv_bfloat16* __restrict__ H2h, __nv_bfloat16* __restrict__ H2l,
            float* __restrict__ Z1, float* __restrict__ Z2,
            const float* __restrict__ b1i, const float* __restrict__ b2i,
            float* __restrict__ c1, float* __restrict__ c2,
            float* __restrict__ hidden)
{
    extern __shared__ char smem[];
    const int z = blockIdx.z;
    const int step = t - z;
    if (step < 0 || step > TT - 1) return;
    if ((int)blockIdx.y * BM >= d_cnt[step]) return;

    const size_t HB = (size_t)BB * HH;
    const int rbA = blockIdx.y * BM, rbB = blockIdx.x * BN;

    const __nv_bfloat16 *Ah, *Al, *Bh, *Bl;
    float *Zp, *cs, *hid;
    const float* bi;
    __nv_bfloat16 *oh, *ol;
    int mode;
    if (z == 0) {            // layer-1 recurrent step
        Ah = H1h + (size_t)step * HB; Al = H1l + (size_t)step * HB;
        Bh = U1h; Bl = U1l;
        Zp = Z1 + (size_t)step * BB * FH; mode = 1;
        bi = b1i; cs = c1;
        oh = H1h + (size_t)(step + 1) * HB; ol = H1l + (size_t)(step + 1) * HB;
        hid = nullptr;
    } else if (z == 1) {     // W2 input-transform slice (h1(step) @ W2 -> Z2 slice)
        Ah = H1h + (size_t)(step + 1) * HB; Al = H1l + (size_t)(step + 1) * HB;
        Bh = W2h; Bl = W2l;
        Zp = Z2 + (size_t)step * BB * FH; mode = 0;
        bi = nullptr; cs = nullptr; oh = nullptr; ol = nullptr; hid = nullptr;
    } else {                 // layer-2 recurrent step + gather
        Ah = H2h + (size_t)step * HB; Al = H2l + (size_t)step * HB;
        Bh = U2h; Bl = U2l;
        Zp = Z2 + (size_t)step * BB * FH; mode = 1;
        bi = b2i; cs = c2;
        oh = H2h + (size_t)(step + 1) * HB; ol = H2l + (size_t)(step + 1) * HB;
        hid = hidden;
    }
    gemm_core(Ah, Al, Bh, Bl, HH, Zp, mode, bi, cs, oh, ol, hid, step, rbA, rbB, smem);
}

// ------------- launch -------------
extern "C" void kernel_launch(void* const* d_in, const int* in_sizes, int n_in,
                              void* d_out, int out_size)
{
    const float* chars  = (const float*)d_in[0];
    const int*   seqlen = (const int*)  d_in[1];
    const float* W1 = (const float*)d_in[2];
    const float* U1 = (const float*)d_in[3];
    const float* b1 = (const float*)d_in[4];
    const float* W2 = (const float*)d_in[5];
    const float* U2 = (const float*)d_in[6];
    const float* b2 = (const float*)d_in[7];
    const float* Wd = (const float*)d_in[8];
    const float* bd = (const float*)d_in[9];
    float* out = (float*)d_out;

    cudaFuncSetAttribute(big_gemm,    cudaFuncAttributeMaxDynamicSharedMemorySize, SMEM_DYN);
    cudaFuncSetAttribute(tick_kernel, cudaFuncAttributeMaxDynamicSharedMemorySize, SMEM_DYN);

    float *Z1, *Z2, *c1, *c2, *hidden, *b1i, *b2i;
    __nv_bfloat16 *Xh, *Xl, *H1h, *H1l, *H2h, *H2l;
    __nv_bfloat16 *W1h, *W1l, *U1h, *U1l, *W2h, *W2l, *U2h, *U2l;
    cudaGetSymbolAddress((void**)&Z1, d_Z1);   cudaGetSymbolAddress((void**)&Z2, d_Z2);
    cudaGetSymbolAddress((void**)&c1, d_c1);   cudaGetSymbolAddress((void**)&c2, d_c2);
    cudaGetSymbolAddress((void**)&hidden, d_hidden);
    cudaGetSymbolAddress((void**)&b1i, d_b1i); cudaGetSymbolAddress((void**)&b2i, d_b2i);
    cudaGetSymbolAddress((void**)&Xh, d_Xh);   cudaGetSymbolAddress((void**)&Xl, d_Xl);
    cudaGetSymbolAddress((void**)&H1h, d_H1h); cudaGetSymbolAddress((void**)&H1l, d_H1l);
    cudaGetSymbolAddress((void**)&H2h, d_H2h); cudaGetSymbolAddress((void**)&H2l, d_H2l);
    cudaGetSymbolAddress((void**)&W1h, d_W1h); cudaGetSymbolAddress((void**)&W1l, d_W1l);
    cudaGetSymbolAddress((void**)&U1h, d_U1h); cudaGetSymbolAddress((void**)&U1l, d_U1l);
    cudaGetSymbolAddress((void**)&W2h, d_W2h); cudaGetSymbolAddress((void**)&W2l, d_W2l);
    cudaGetSymbolAddress((void**)&U2h, d_U2h); cudaGetSymbolAddress((void**)&U2l, d_U2l);

    split_w<<<(FH*DIN)/256, 256>>>(W1, W1h, W1l, DIN);
    split_w<<<(FH*HH)/256, 256>>>(U1, U1h, U1l, HH);
    split_w<<<(FH*HH)/256, 256>>>(W2, W2h, W2l, HH);
    split_w<<<(FH*HH)/256, 256>>>(U2, U2h, U2l, HH);
    interleave_bias<<<FH/256, 256>>>(b1, b1i);
    interleave_bias<<<FH/256, 256>>>(b2, b2i);
    seq_sort<<<1, BB>>>(seqlen);
    seq_cnt<<<1, TT+1>>>(seqlen);
    split_chars<<<(TBROWS*64)/256, 256>>>(chars, Xh, Xl);
    init_states<<<(BB*HH)/256, 256>>>();

    // layer-1 input transform: Z1 = X @ W1t^T (tiles skipped past cnt[t])
    dim3 gBig(FH/BN, TBROWS/BM);   // (32, 1024)
    big_gemm<<<gBig, 128, SMEM_DYN>>>(Xh, Xl, W1h, W1l, DIN, Z1);

    // software-pipelined ticks: l1(t) || W2-slice(t-1) || l2(t-2)
    dim3 gTick(FH/BN, BB/BM, 3);   // (32, 8, 3)
    for (int t = 0; t <= TT + 1; t++)
        tick_kernel<<<gTick, 128, SMEM_DYN>>>(t, U1h, U1l, W2h, W2l, U2h, U2l,
                                              H1h, H1l, H2h, H2l, Z1, Z2,
                                              b1i, b2i, c1, c2, hidden);

    dense_relu<<<BB, 128>>>(hidden, Wd, bd, out);
}

// round 11
// speedup vs baseline: 2.2905x; 1.1584x over previous
#include <cuda_runtime.h>
#include <cuda_bf16.h>
#include <mma.h>
#include <cstdint>

using namespace nvcuda;

#define BB   512
#define TT   128
#define DIN  256
#define HH   1024
#define FH   4096
#define TBROWS (TT*BB)

#define BM 64
#define BN 128
#define ABYTES 5120u          // 64 rows * 80 B
#define BBYTES 10240u         // 128 rows * 80 B
#define STG 30720u            // 2*A + 2*B per stage
#define NSTAGE 3
#define SMEM_DYN 92160        // 3 stages
#define LDS_EP 132            // epilogue smem stride (floats)
#define NWORKER 296           // 148 SMs x 2 CTAs (<= capacity on 152-SM GB300 too)
#define TILE_MAX 100352

// ------------- device scratch (no allocation allowed) -------------
__device__ float d_Z1[(size_t)TBROWS*FH];
__device__ float d_Z2[(size_t)TBROWS*FH];
__device__ float d_c1[BB*HH], d_c2[BB*HH];
__device__ float d_hidden[BB*HH];
__device__ float d_b1i[FH], d_b2i[FH];
__device__ int   d_pos[BB], d_orig[BB], d_seqP[BB], d_cnt[TT+1];
__device__ int   d_tiles[TILE_MAX];
__device__ int   d_ntiles;
__device__ int   d_ticket;
__device__ int   d_done[3*TT*8];
__device__ __nv_bfloat16 d_Xh[(size_t)TBROWS*DIN], d_Xl[(size_t)TBROWS*DIN];
__device__ __nv_bfloat16 d_H1h[(size_t)(TT+1)*BB*HH], d_H1l[(size_t)(TT+1)*BB*HH];
__device__ __nv_bfloat16 d_H2h[(size_t)(TT+1)*BB*HH], d_H2l[(size_t)(TT+1)*BB*HH];
__device__ __nv_bfloat16 d_W1h[(size_t)FH*DIN], d_W1l[(size_t)FH*DIN];
__device__ __nv_bfloat16 d_U1h[(size_t)FH*HH],  d_U1l[(size_t)FH*HH];
__device__ __nv_bfloat16 d_W2h[(size_t)FH*HH],  d_W2l[(size_t)FH*HH];
__device__ __nv_bfloat16 d_U2h[(size_t)FH*HH],  d_U2l[(size_t)FH*HH];

// ------------- PTX helpers (Ampere-level: valid on plain sm_103) ------
__device__ __forceinline__ uint32_t smem_u32(const void* p) {
    uint32_t a;
    asm("{ .reg .u64 t; cvta.to.shared.u64 t, %1; cvt.u32.u64 %0, t; }" : "=r"(a) : "l"(p));
    return a;
}
__device__ __forceinline__ void cp16(uint32_t d, const void* s) {
    asm volatile("cp.async.cg.shared.global [%0], [%1], 16;" :: "r"(d), "l"(s) : "memory");
}
__device__ __forceinline__ void cp_commit() { asm volatile("cp.async.commit_group;" ::: "memory"); }
__device__ __forceinline__ void cp_wait1()  { asm volatile("cp.async.wait_group 1;" ::: "memory"); }
// L1-bypassing float4 ld/st (c-state is cross-CTA RMW within one launch)
__device__ __forceinline__ float4 ld_cg_f4(const float* p) {
    float4 v;
    asm volatile("ld.global.cg.v4.f32 {%0,%1,%2,%3}, [%4];"
                 : "=f"(v.x), "=f"(v.y), "=f"(v.z), "=f"(v.w) : "l"(p));
    return v;
}
__device__ __forceinline__ void st_cg_f4(float* p, float4 v) {
    asm volatile("st.global.cg.v4.f32 [%0], {%1,%2,%3,%4};"
                 :: "l"(p), "f"(v.x), "f"(v.y), "f"(v.z), "f"(v.w) : "memory");
}

// ------------- preprocessing -------------
__global__ void split_w(const float* __restrict__ W, __nv_bfloat16* __restrict__ oh,
                        __nv_bfloat16* __restrict__ ol, int K)
{
    size_t i = (size_t)blockIdx.x * blockDim.x + threadIdx.x;
    int k = (int)(i % K), n = (int)(i / K);
    float x = W[(size_t)k * FH + (n & 3) * HH + (n >> 2)];
    __nv_bfloat16 h = __float2bfloat16(x);
    oh[i] = h;
    ol[i] = __float2bfloat16(x - __bfloat162float(h));
}
__global__ void interleave_bias(const float* __restrict__ b, float* __restrict__ bi)
{
    int n = blockIdx.x * blockDim.x + threadIdx.x;
    bi[n] = b[(n & 3) * HH + (n >> 2)];
}
__global__ void seq_sort(const int* __restrict__ seqlen)
{
    int b = threadIdx.x;
    int s = seqlen[b];
    int pos = 0;
    for (int j = 0; j < BB; j++) {
        int sj = seqlen[j];
        pos += (sj > s) || (sj == s && j < b);
    }
    d_pos[b] = pos;
    d_orig[pos] = b;
    d_seqP[pos] = s;
}
__global__ void seq_cnt(const int* __restrict__ seqlen)
{
    int t = threadIdx.x;
    if (t > TT) return;
    int c = 0;
    for (int j = 0; j < BB; j++) c += (seqlen[j] >= t + 1);
    d_cnt[t] = c;
}
__global__ void split_chars(const float* __restrict__ chars,
                            __nv_bfloat16* __restrict__ xh, __nv_bfloat16* __restrict__ xl)
{
    int idx = blockIdx.x * blockDim.x + threadIdx.x;
    int d4 = idx & 63, rest = idx >> 6;
    int b = rest & (BB - 1), t = rest >> 9;
    float4 v = *(const float4*)(chars + ((size_t)b * TT + t) * DIN + d4 * 4);
    size_t o = ((size_t)t * BB + d_pos[b]) * DIN + d4 * 4;
    float vv[4] = {v.x, v.y, v.z, v.w};
    #pragma unroll
    for (int e = 0; e < 4; e++) {
        __nv_bfloat16 h = __float2bfloat16(vv[e]);
        xh[o + e] = h;
        xl[o + e] = __float2bfloat16(vv[e] - __bfloat162float(h));
    }
}
__global__ void init_states()
{
    int i = blockIdx.x * blockDim.x + threadIdx.x;  // BB*HH
    d_c1[i] = 0.f; d_c2[i] = 0.f;
    __nv_bfloat16 z = __float2bfloat16(0.f);
    d_H1h[i] = z; d_H1l[i] = z; d_H2h[i] = z; d_H2l[i] = z;
    if (i < 3*TT*8) d_done[i] = 0;
    if (i == 0) d_ticket = 0;
}
// tile list: for tick 0..129: l1(tick), w2(tick-1), l2(tick-2); active y-tiles x 32
__global__ void build_tiles()
{
    int id = blockIdx.x * blockDim.x + threadIdx.x;   // 0..389
    if (id >= 390) return;
    int off = 0;
    for (int j = 0; j < id; j++) {
        int s = j / 3 - (j % 3);
        if (s >= 0 && s < TT) off += ((d_cnt[s] + 63) >> 6) * 32;
    }
    if (id == 0) {
        int tot = 0;
        for (int j = 0; j < 390; j++) {
            int s = j / 3 - (j % 3);
            if (s >= 0 && s < TT) tot += ((d_cnt[s] + 63) >> 6) * 32;
        }
        d_ntiles = tot;
    }
    int role = id % 3, step = id / 3 - role;
    if (step < 0 || step >= TT) return;
    int ny = (d_cnt[step] + 63) >> 6;
    for (int y = 0; y < ny; y++)
        for (int x = 0; x < 32; x++)
            d_tiles[off++] = (role << 16) | (step << 8) | (y << 5) | x;
}
__global__ void dense_relu(const float* __restrict__ hidden, const float* __restrict__ Wd,
                           const float* __restrict__ bd, float* __restrict__ out)
{
    __shared__ float buf[3][128];
    int b = blockIdx.x, tid = threadIdx.x;
    const float* hb = hidden + (size_t)b * HH;
    float s0 = 0.f, s1 = 0.f, s2 = 0.f;
    for (int k = tid; k < HH; k += 128) {
        float hv = hb[k];
        s0 = fmaf(hv, Wd[k*3+0], s0); s1 = fmaf(hv, Wd[k*3+1], s1); s2 = fmaf(hv, Wd[k*3+2], s2);
    }
    buf[0][tid] = s0; buf[1][tid] = s1; buf[2][tid] = s2;
    __syncthreads();
    for (int s = 64; s > 0; s >>= 1) {
        if (tid < s) { buf[0][tid]+=buf[0][tid+s]; buf[1][tid]+=buf[1][tid+s]; buf[2][tid]+=buf[2][tid+s]; }
        __syncthreads();
    }
    if (tid < 3) out[b*3 + tid] = fmaxf(buf[tid][0] + bd[tid], 0.f);
}

// ------------- GEMM core -------------
// D[64,128] = A[64,K] @ B[128,K]^T (K-major, hi/lo split, 3 MMA terms)
// mode 0: Z[rowA,n] = D.  mode 1: z = D + Z + bias -> gates -> c,h(split bf16).
__device__ __forceinline__ void gemm_core(
    const __nv_bfloat16* __restrict__ Ah, const __nv_bfloat16* __restrict__ Al,
    const __nv_bfloat16* __restrict__ Bh, const __nv_bfloat16* __restrict__ Bl,
    int K, float* __restrict__ Z, int mode,
    const float* __restrict__ biasI, float* __restrict__ cst,
    __nv_bfloat16* __restrict__ hh, __nv_bfloat16* __restrict__ hl,
    float* __restrict__ hidden, int step, int rbA, int rbB, char* smem)
{
    const int tid = threadIdx.x, wid = tid >> 5;
    const int wr = wid & 1, wc = wid >> 1;
    const int nch = K >> 5;
    const uint32_t sbase = smem_u32(smem);

    auto load_chunk = [&](int ch, int buf) {
        if (ch < nch) {
            const int k0 = ch << 5;
            const uint32_t st = sbase + (uint32_t)buf * STG;
            const __nv_bfloat16* sa[2] = {Ah, Al};
            const __nv_bfloat16* sbp[2] = {Bh, Bl};
            #pragma unroll
            for (int op = 0; op < 2; op++) {
                const __nv_bfloat16* src = sa[op] + (size_t)rbA * K + k0;
                uint32_t sb = st + op * ABYTES;
                #pragma unroll
                for (int it = 0; it < 2; it++) {
                    int ck = it * 128 + tid;
                    int r = ck >> 2, c = ck & 3;
                    cp16(sb + r * 80 + c * 16, src + (size_t)r * K + c * 8);
                }
            }
            #pragma unroll
            for (int op = 0; op < 2; op++) {
                const __nv_bfloat16* src = sbp[op] + (size_t)rbB * K + k0;
                uint32_t sb = st + 2 * ABYTES + op * BBYTES;
                #pragma unroll
                for (int it = 0; it < 4; it++) {
                    int ck = it * 128 + tid;
                    int r = ck >> 2, c = ck & 3;
                    cp16(sb + r * 80 + c * 16, src + (size_t)r * K + c * 8);
                }
            }
        }
        cp_commit();
    };

    wmma::fragment<wmma::accumulator, 16, 16, 16, float> acc[2][4];
    #pragma unroll
    for (int m = 0; m < 2; m++)
        #pragma unroll
        for (int n = 0; n < 4; n++) wmma::fill_fragment(acc[m][n], 0.f);

    load_chunk(0, 0); load_chunk(1, 1);

    for (int i = 0; i < nch; i++) {
        cp_wait1();
        __syncthreads();
        load_chunk(i + 2, (i + 2) % NSTAGE);
        const __nv_bfloat16* sb = (const __nv_bfloat16*)(smem + (size_t)(i % NSTAGE) * STG);
        const __nv_bfloat16* sAh_ = sb;
        const __nv_bfloat16* sAl_ = sb + 2560;
        const __nv_bfloat16* sBh_ = sb + 5120;
        const __nv_bfloat16* sBl_ = sb + 10240;
        #pragma unroll
        for (int kk = 0; kk < 2; kk++) {
            wmma::fragment<wmma::matrix_a, 16, 16, 16, __nv_bfloat16, wmma::row_major> fah[2], fal[2];
            wmma::fragment<wmma::matrix_b, 16, 16, 16, __nv_bfloat16, wmma::col_major> fbh[4], fbl[4];
            #pragma unroll
            for (int m = 0; m < 2; m++) {
                wmma::load_matrix_sync(fah[m], sAh_ + (wr*32 + m*16)*40 + kk*16, 40);
                wmma::load_matrix_sync(fal[m], sAl_ + (wr*32 + m*16)*40 + kk*16, 40);
            }
            #pragma unroll
            for (int n = 0; n < 4; n++) {
                wmma::load_matrix_sync(fbh[n], sBh_ + (wc*64 + n*16)*40 + kk*16, 40);
                wmma::load_matrix_sync(fbl[n], sBl_ + (wc*64 + n*16)*40 + kk*16, 40);
            }
            #pragma unroll
            for (int m = 0; m < 2; m++)
                #pragma unroll
                for (int n = 0; n < 4; n++) {
                    wmma::mma_sync(acc[m][n], fah[m], fbh[n], acc[m][n]);
                    wmma::mma_sync(acc[m][n], fal[m], fbh[n], acc[m][n]);
                    wmma::mma_sync(acc[m][n], fah[m], fbl[n], acc[m][n]);
                }
        }
    }

    if (mode == 0) {
        float* dst = Z + (size_t)rbA * FH + rbB;
        #pragma unroll
        for (int m = 0; m < 2; m++)
            #pragma unroll
            for (int n = 0; n < 4; n++)
                wmma::store_matrix_sync(dst + (size_t)(wr*32 + m*16) * FH + wc*64 + n*16,
                                        acc[m][n], FH, wmma::mem_row_major);
        return;
    }

    // ---- fused LSTM gate epilogue (64 rows) ----
    __syncthreads();
    float* Zs = (float*)smem;
    #pragma unroll
    for (int m = 0; m < 2; m++)
        #pragma unroll
        for (int n = 0; n < 4; n++)
            wmma::store_matrix_sync(Zs + (wr*32 + m*16) * LDS_EP + wc*64 + n*16,
                                    acc[m][n], LDS_EP, wmma::mem_row_major);
    __syncthreads();

    const int rl = tid >> 1, half = tid & 1;
    const int p = rbA + rl;
    const int n0 = rbB + half * 64;
    const int jb = n0 >> 2;
    const float* zs = Zs + rl * LDS_EP + half * 64;
    const float4* zg = (const float4*)(Z + (size_t)p * FH + n0);
    const float4* bi4 = (const float4*)(biasI + n0);
    float* crow = cst + (size_t)p * HH + jb;
    const bool gath = (hidden != nullptr) && (d_seqP[p] - 1 == step);
    float* hidrow = gath ? (hidden + (size_t)d_orig[p] * HH + jb) : nullptr;

    // c-state via L1-bypassing loads (cross-CTA RMW within a single launch)
    float cold[16];
    #pragma unroll
    for (int q = 0; q < 4; q++) {
        float4 cv = ld_cg_f4(crow + q*4);
        cold[q*4+0] = cv.x; cold[q*4+1] = cv.y; cold[q*4+2] = cv.z; cold[q*4+3] = cv.w;
    }

    float cn[16]; __nv_bfloat16 hb[16], lb[16];
    #pragma unroll
    for (int g = 0; g < 16; g++) {
        float4 zv = zg[g], bv = bi4[g];
        float vi = zs[g*4+0] + zv.x + bv.x;
        float vf = zs[g*4+1] + zv.y + bv.y;
        float vg = zs[g*4+2] + zv.z + bv.z;
        float vo = zs[g*4+3] + zv.w + bv.w;
        float ig = 1.f / (1.f + __expf(-vi));
        float fg = 1.f / (1.f + __expf(-vf));
        float gg = tanhf(vg);
        float og = 1.f / (1.f + __expf(-vo));
        float c_ = fg * cold[g] + ig * gg;
        cn[g] = c_;
        float hv = og * tanhf(c_);
        __nv_bfloat16 hi_ = __float2bfloat16(hv);
        hb[g] = hi_;
        lb[g] = __float2bfloat16(hv - __bfloat162float(hi_));
        if (gath) hidrow[g] = hv;
    }
    #pragma unroll
    for (int q = 0; q < 4; q++)
        st_cg_f4(crow + q*4, make_float4(cn[q*4], cn[q*4+1], cn[q*4+2], cn[q*4+3]));
    *(uint4*)(hh + (size_t)p * HH + jb)     = ((uint4*)hb)[0];
    *(uint4*)(hh + (size_t)p * HH + jb + 8) = ((uint4*)hb)[1];
    *(uint4*)(hl + (size_t)p * HH + jb)     = ((uint4*)lb)[0];
    *(uint4*)(hl + (size_t)p * HH + jb + 8) = ((uint4*)lb)[1];
}

// big input transform: Z1 = X @ W1t^T, skip tiles past cnt[t]
__global__ void __launch_bounds__(128, 2)
big_gemm(const __nv_bfloat16* __restrict__ Ah, const __nv_bfloat16* __restrict__ Al,
         const __nv_bfloat16* __restrict__ Bh, const __nv_bfloat16* __restrict__ Bl,
         int K, float* __restrict__ Z)
{
    extern __shared__ char smem[];
    int row0 = blockIdx.y * BM;
    int tt = row0 >> 9, p0 = row0 & 511;
    if (p0 >= d_cnt[tt]) return;
    gemm_core(Ah, Al, Bh, Bl, K, Z, 0, nullptr, nullptr, nullptr, nullptr,
              nullptr, 0, row0, blockIdx.x * BN, smem);
}

// ------------- persistent worker: ticket + per-(role,step,y) dataflow ------
__device__ __forceinline__ void wait_flag(int idx) {
    volatile int* f = (volatile int*)d_done;
    while (f[idx] < 32) __nanosleep(256);
}

__global__ void __launch_bounds__(128, 2)
worker(const __nv_bfloat16* __restrict__ U1h, const __nv_bfloat16* __restrict__ U1l,
       const __nv_bfloat16* __restrict__ W2h, const __nv_bfloat16* __restrict__ W2l,
       const __nv_bfloat16* __restrict__ U2h, const __nv_bfloat16* __restrict__ U2l,
       __nv_bfloat16* __restrict__ H1h, __nv_bfloat16* __restrict__ H1l,
       __nv_bfloat16* __restrict__ H2h, __nv_bfloat16* __restrict__ H2l,
       float* __restrict__ Z1, float* __restrict__ Z2,
       const float* __restrict__ b1i, const float* __restrict__ b2i,
       float* __restrict__ c1, float* __restrict__ c2,
       float* __restrict__ hidden)
{
    extern __shared__ char smem[];
    __shared__ int s_w;
    const int tid = threadIdx.x;
    const size_t HB = (size_t)BB * HH;

    for (;;) {
        __syncthreads();
        if (tid == 0) {
            int k = atomicAdd(&d_ticket, 1);
            s_w = (k < d_ntiles) ? d_tiles[k] : -1;
        }
        __syncthreads();
        const int w = s_w;
        if (w < 0) break;
        const int role = w >> 16, step = (w >> 8) & 255, y = (w >> 5) & 7, x = w & 31;

        // dependency waits (thread 0 spins; others idle at barrier)
        if (tid == 0) {
            if (role == 0) {
                if (step > 0) wait_flag(0*TT*8 + (step-1)*8 + y);
            } else if (role == 1) {
                wait_flag(0*TT*8 + step*8 + y);
            } else {
                wait_flag(1*TT*8 + step*8 + y);
                if (step > 0) wait_flag(2*TT*8 + (step-1)*8 + y);
            }
            __threadfence();
        }
        __syncthreads();

        const int rbA = y * BM, rbB = x * BN;
        if (role == 0) {          // layer-1 recurrent step
            gemm_core(H1h + (size_t)step * HB, H1l + (size_t)step * HB, U1h, U1l,
                      HH, Z1 + (size_t)step * BB * FH, 1, b1i, c1,
                      H1h + (size_t)(step+1) * HB, H1l + (size_t)(step+1) * HB,
                      nullptr, step, rbA, rbB, smem);
        } else if (role == 1) {   // W2 input-transform slice: h1(step) @ W2 -> Z2 slice
            gemm_core(H1h + (size_t)(step+1) * HB, H1l + (size_t)(step+1) * HB, W2h, W2l,
                      HH, Z2 + (size_t)step * BB * FH, 0, nullptr, nullptr,
                      nullptr, nullptr, nullptr, step, rbA, rbB, smem);
        } else {                  // layer-2 recurrent step + gather
            gemm_core(H2h + (size_t)step * HB, H2l + (size_t)step * HB, U2h, U2l,
                      HH, Z2 + (size_t)step * BB * FH, 1, b2i, c2,
                      H2h + (size_t)(step+1) * HB, H2l + (size_t)(step+1) * HB,
                      hidden, step, rbA, rbB, smem);
        }

        __threadfence();
        __syncthreads();
        if (tid == 0) atomicAdd(&d_done[role*TT*8 + step*8 + y], 1);
    }
}

// ------------- launch -------------
extern "C" void kernel_launch(void* const* d_in, const int* in_sizes, int n_in,
                              void* d_out, int out_size)
{
    const float* chars  = (const float*)d_in[0];
    const int*   seqlen = (const int*)  d_in[1];
    const float* W1 = (const float*)d_in[2];
    const float* U1 = (const float*)d_in[3];
    const float* b1 = (const float*)d_in[4];
    const float* W2 = (const float*)d_in[5];
    const float* U2 = (const float*)d_in[6];
    const float* b2 = (const float*)d_in[7];
    const float* Wd = (const float*)d_in[8];
    const float* bd = (const float*)d_in[9];
    float* out = (float*)d_out;

    cudaFuncSetAttribute(big_gemm, cudaFuncAttributeMaxDynamicSharedMemorySize, SMEM_DYN);
    cudaFuncSetAttribute(worker,   cudaFuncAttributeMaxDynamicSharedMemorySize, SMEM_DYN);

    float *Z1, *Z2, *c1, *c2, *hidden, *b1i, *b2i;
    __nv_bfloat16 *Xh, *Xl, *H1h, *H1l, *H2h, *H2l;
    __nv_bfloat16 *W1h, *W1l, *U1h, *U1l, *W2h, *W2l, *U2h, *U2l;
    cudaGetSymbolAddress((void**)&Z1, d_Z1);   cudaGetSymbolAddress((void**)&Z2, d_Z2);
    cudaGetSymbolAddress((void**)&c1, d_c1);   cudaGetSymbolAddress((void**)&c2, d_c2);
    cudaGetSymbolAddress((void**)&hidden, d_hidden);
    cudaGetSymbolAddress((void**)&b1i, d_b1i); cudaGetSymbolAddress((void**)&b2i, d_b2i);
    cudaGetSymbolAddress((void**)&Xh, d_Xh);   cudaGetSymbolAddress((void**)&Xl, d_Xl);
    cudaGetSymbolAddress((void**)&H1h, d_H1h); cudaGetSymbolAddress((void**)&H1l, d_H1l);
    cudaGetSymbolAddress((void**)&H2h, d_H2h); cudaGetSymbolAddress((void**)&H2l, d_H2l);
    cudaGetSymbolAddress((void**)&W1h, d_W1h); cudaGetSymbolAddress((void**)&W1l, d_W1l);
    cudaGetSymbolAddress((void**)&U1h, d_U1h); cudaGetSymbolAddress((void**)&U1l, d_U1l);
    cudaGetSymbolAddress((void**)&W2h, d_W2h); cudaGetSymbolAddress((void**)&W2l, d_W2l);
    cudaGetSymbolAddress((void**)&U2h, d_U2h); cudaGetSymbolAddress((void**)&U2l, d_U2l);

    split_w<<<(FH*DIN)/256, 256>>>(W1, W1h, W1l, DIN);
    split_w<<<(FH*HH)/256, 256>>>(U1, U1h, U1l, HH);
    split_w<<<(FH*HH)/256, 256>>>(W2, W2h, W2l, HH);
    split_w<<<(FH*HH)/256, 256>>>(U2, U2h, U2l, HH);
    interleave_bias<<<FH/256, 256>>>(b1, b1i);
    interleave_bias<<<FH/256, 256>>>(b2, b2i);
    seq_sort<<<1, BB>>>(seqlen);
    seq_cnt<<<1, TT+1>>>(seqlen);
    split_chars<<<(TBROWS*64)/256, 256>>>(chars, Xh, Xl);
    init_states<<<(BB*HH)/256, 256>>>();
    build_tiles<<<2, 256>>>();

    // layer-1 input transform: Z1 = X @ W1t^T
    dim3 gBig(FH/BN, TBROWS/BM);
    big_gemm<<<gBig, 128, SMEM_DYN>>>(Xh, Xl, W1h, W1l, DIN, Z1);

    // persistent dataflow worker: l1 / W2-slice / l2 tiles with flag deps
    worker<<<NWORKER, 128, SMEM_DYN>>>(U1h, U1l, W2h, W2l, U2h, U2l,
                                       H1h, H1l, H2h, H2l, Z1, Z2,
                                       b1i, b2i, c1, c2, hidden);

    dense_relu<<<BB, 128>>>(hidden, Wd, bd, out);
}

// round 13
// speedup vs baseline: 2.2915x; 1.0004x over previous
#include <cuda_runtime.h>
#include <cuda_bf16.h>
#include <mma.h>
#include <cstdint>

using namespace nvcuda;

#define BB   512
#define TT   128
#define DIN  256
#define HH   1024
#define FH   4096
#define TBROWS (TT*BB)

#define BM 64
#define BN 128
#define ABYTES 5120u          // 64 rows * 80 B
#define BBYTES 10240u         // 128 rows * 80 B
#define STG 30720u            // BM64 stage: 2*A + 2*B
#define STG32 25600u          // BM32 stage: 2*2560 + 2*10240
#define NSTAGE 3
#define SMEM_DYN 92160
#define LDS_EP 132
#define NWORKER 296
#define TILE_MAX 131072
#define NSLOT 524             // 4 pre + 130 ticks * 4

// ------------- device scratch (no allocation allowed) -------------
__device__ float d_Z1[(size_t)TBROWS*FH];
__device__ float d_Z2[(size_t)TBROWS*FH];
__device__ float d_c1[BB*HH], d_c2[BB*HH];
__device__ float d_hidden[BB*HH];
__device__ float d_b1i[FH], d_b2i[FH];
__device__ int   d_pos[BB], d_orig[BB], d_seqP[BB], d_cnt[TT+1];
__device__ int   d_tiles[TILE_MAX];
__device__ int   d_ntiles;
__device__ int   d_ticket;
__device__ int   d_done[4*TT*8];
__device__ __nv_bfloat16 d_Xh[(size_t)TBROWS*DIN], d_Xl[(size_t)TBROWS*DIN];
__device__ __nv_bfloat16 d_H1h[(size_t)(TT+1)*BB*HH], d_H1l[(size_t)(TT+1)*BB*HH];
__device__ __nv_bfloat16 d_H2h[(size_t)(TT+1)*BB*HH], d_H2l[(size_t)(TT+1)*BB*HH];
__device__ __nv_bfloat16 d_W1h[(size_t)FH*DIN], d_W1l[(size_t)FH*DIN];
__device__ __nv_bfloat16 d_U1h[(size_t)FH*HH],  d_U1l[(size_t)FH*HH];
__device__ __nv_bfloat16 d_W2h[(size_t)FH*HH],  d_W2l[(size_t)FH*HH];
__device__ __nv_bfloat16 d_U2h[(size_t)FH*HH],  d_U2l[(size_t)FH*HH];

// ------------- PTX helpers (Ampere-level: valid on plain sm_103) ------
__device__ __forceinline__ uint32_t smem_u32(const void* p) {
    uint32_t a;
    asm("{ .reg .u64 t; cvta.to.shared.u64 t, %1; cvt.u32.u64 %0, t; }" : "=r"(a) : "l"(p));
    return a;
}
__device__ __forceinline__ void cp16(uint32_t d, const void* s) {
    asm volatile("cp.async.cg.shared.global [%0], [%1], 16;" :: "r"(d), "l"(s) : "memory");
}
__device__ __forceinline__ void cp_commit() { asm volatile("cp.async.commit_group;" ::: "memory"); }
__device__ __forceinline__ void cp_wait1()  { asm volatile("cp.async.wait_group 1;" ::: "memory"); }
__device__ __forceinline__ float4 ld_cg_f4(const float* p) {
    float4 v;
    asm volatile("ld.global.cg.v4.f32 {%0,%1,%2,%3}, [%4];"
                 : "=f"(v.x), "=f"(v.y), "=f"(v.z), "=f"(v.w) : "l"(p));
    return v;
}
__device__ __forceinline__ void st_cg_f4(float* p, float4 v) {
    asm volatile("st.global.cg.v4.f32 [%0], {%1,%2,%3,%4};"
                 :: "l"(p), "f"(v.x), "f"(v.y), "f"(v.z), "f"(v.w) : "memory");
}

// ------------- preprocessing -------------
__global__ void split_w(const float* __restrict__ W, __nv_bfloat16* __restrict__ oh,
                        __nv_bfloat16* __restrict__ ol, int K)
{
    size_t i = (size_t)blockIdx.x * blockDim.x + threadIdx.x;
    int k = (int)(i % K), n = (int)(i / K);
    float x = W[(size_t)k * FH + (n & 3) * HH + (n >> 2)];
    __nv_bfloat16 h = __float2bfloat16(x);
    oh[i] = h;
    ol[i] = __float2bfloat16(x - __bfloat162float(h));
}
__global__ void interleave_bias(const float* __restrict__ b, float* __restrict__ bi)
{
    int n = blockIdx.x * blockDim.x + threadIdx.x;
    bi[n] = b[(n & 3) * HH + (n >> 2)];
}
__global__ void seq_sort(const int* __restrict__ seqlen)
{
    int b = threadIdx.x;
    int s = seqlen[b];
    int pos = 0;
    for (int j = 0; j < BB; j++) {
        int sj = seqlen[j];
        pos += (sj > s) || (sj == s && j < b);
    }
    d_pos[b] = pos;
    d_orig[pos] = b;
    d_seqP[pos] = s;
}
__global__ void seq_cnt(const int* __restrict__ seqlen)
{
    int t = threadIdx.x;
    if (t > TT) return;
    int c = 0;
    for (int j = 0; j < BB; j++) c += (seqlen[j] >= t + 1);
    d_cnt[t] = c;
}
__global__ void split_chars(const float* __restrict__ chars,
                            __nv_bfloat16* __restrict__ xh, __nv_bfloat16* __restrict__ xl)
{
    int idx = blockIdx.x * blockDim.x + threadIdx.x;
    int d4 = idx & 63, rest = idx >> 6;
    int b = rest & (BB - 1), t = rest >> 9;
    float4 v = *(const float4*)(chars + ((size_t)b * TT + t) * DIN + d4 * 4);
    size_t o = ((size_t)t * BB + d_pos[b]) * DIN + d4 * 4;
    float vv[4] = {v.x, v.y, v.z, v.w};
    #pragma unroll
    for (int e = 0; e < 4; e++) {
        __nv_bfloat16 h = __float2bfloat16(vv[e]);
        xh[o + e] = h;
        xl[o + e] = __float2bfloat16(vv[e] - __bfloat162float(h));
    }
}
__global__ void init_states()
{
    int i = blockIdx.x * blockDim.x + threadIdx.x;  // BB*HH threads
    d_c1[i] = 0.f; d_c2[i] = 0.f;
    __nv_bfloat16 z = __float2bfloat16(0.f);
    d_H1h[i] = z; d_H1l[i] = z; d_H2h[i] = z; d_H2l[i] = z;
    if (i < 4*TT*8) d_done[i] = 0;
    if (i == 0) d_ticket = 0;
}

// slot -> (role, step). roles: 0=l1, 1=w2, 2=l2, 3=w1. -1 if invalid.
__device__ __forceinline__ int slot_decode(int j, int* role)
{
    if (j < 4) { *role = 3; return j; }
    int t = (j - 4) >> 2, q = (j - 4) & 3;
    int r, s;
    if (q == 0)      { r = 3; s = t + 4; }
    else if (q == 1) { r = 0; s = t; }
    else if (q == 2) { r = 1; s = t - 1; }
    else             { r = 2; s = t - 2; }
    *role = r;
    return (s >= 0 && s < TT) ? s : -1;
}
// tile list: lookahead w1, then per tick: w1(t+4), l1(t), w2(t-1), l2(t-2)
__global__ void build_tiles()
{
    int id = blockIdx.x * blockDim.x + threadIdx.x;
    if (id >= NSLOT) return;
    int off = 0;
    for (int j = 0; j < id; j++) {
        int r, s = slot_decode(j, &r);
        if (s >= 0) off += ((d_cnt[s] + 63) >> 6) * 32;
    }
    if (id == 0) {
        int tot = 0;
        for (int j = 0; j < NSLOT; j++) {
            int r, s = slot_decode(j, &r);
            if (s >= 0) tot += ((d_cnt[s] + 63) >> 6) * 32;
        }
        d_ntiles = tot;
    }
    int role, step = slot_decode(id, &role);
    if (step < 0) return;
    int c = d_cnt[step];
    int ny = (c + 63) >> 6;
    for (int y = 0; y < ny; y++) {
        int half = (c <= y * 64 + 32) ? 1 : 0;
        for (int x = 0; x < 32; x++)
            d_tiles[off++] = x | (y << 5) | (step << 8) | (role << 15) | (half << 17);
    }
}
__global__ void dense_relu(const float* __restrict__ hidden, const float* __restrict__ Wd,
                           const float* __restrict__ bd, float* __restrict__ out)
{
    __shared__ float buf[3][128];
    int b = blockIdx.x, tid = threadIdx.x;
    const float* hb = hidden + (size_t)b * HH;
    float s0 = 0.f, s1 = 0.f, s2 = 0.f;
    for (int k = tid; k < HH; k += 128) {
        float hv = hb[k];
        s0 = fmaf(hv, Wd[k*3+0], s0); s1 = fmaf(hv, Wd[k*3+1], s1); s2 = fmaf(hv, Wd[k*3+2], s2);
    }
    buf[0][tid] = s0; buf[1][tid] = s1; buf[2][tid] = s2;
    __syncthreads();
    for (int s = 64; s > 0; s >>= 1) {
        if (tid < s) { buf[0][tid]+=buf[0][tid+s]; buf[1][tid]+=buf[1][tid+s]; buf[2][tid]+=buf[2][tid+s]; }
        __syncthreads();
    }
    if (tid < 3) out[b*3 + tid] = fmaxf(buf[tid][0] + bd[tid], 0.f);
}

// ------------- GEMM core, BM=64 -------------
__device__ __forceinline__ void gemm_core(
    const __nv_bfloat16* __restrict__ Ah, const __nv_bfloat16* __restrict__ Al,
    const __nv_bfloat16* __restrict__ Bh, const __nv_bfloat16* __restrict__ Bl,
    int K, float* __restrict__ Z, int mode,
    const float* __restrict__ biasI, float* __restrict__ cst,
    __nv_bfloat16* __restrict__ hh, __nv_bfloat16* __restrict__ hl,
    float* __restrict__ hidden, int step, int rbA, int rbB, char* smem)
{
    const int tid = threadIdx.x, wid = tid >> 5;
    const int wr = wid & 1, wc = wid >> 1;
    const int nch = K >> 5;
    const uint32_t sbase = smem_u32(smem);

    auto load_chunk = [&](int ch, int buf) {
        if (ch < nch) {
            const int k0 = ch << 5;
            const uint32_t st = sbase + (uint32_t)buf * STG;
            const __nv_bfloat16* sa[2] = {Ah, Al};
            const __nv_bfloat16* sbp[2] = {Bh, Bl};
            #pragma unroll
            for (int op = 0; op < 2; op++) {
                const __nv_bfloat16* src = sa[op] + (size_t)rbA * K + k0;
                uint32_t sb = st + op * ABYTES;
                #pragma unroll
                for (int it = 0; it < 2; it++) {
                    int ck = it * 128 + tid;
                    int r = ck >> 2, c = ck & 3;
                    cp16(sb + r * 80 + c * 16, src + (size_t)r * K + c * 8);
                }
            }
            #pragma unroll
            for (int op = 0; op < 2; op++) {
                const __nv_bfloat16* src = sbp[op] + (size_t)rbB * K + k0;
                uint32_t sb = st + 2 * ABYTES + op * BBYTES;
                #pragma unroll
                for (int it = 0; it < 4; it++) {
                    int ck = it * 128 + tid;
                    int r = ck >> 2, c = ck & 3;
                    cp16(sb + r * 80 + c * 16, src + (size_t)r * K + c * 8);
                }
            }
        }
        cp_commit();
    };

    wmma::fragment<wmma::accumulator, 16, 16, 16, float> acc[2][4];
    #pragma unroll
    for (int m = 0; m < 2; m++)
        #pragma unroll
        for (int n = 0; n < 4; n++) wmma::fill_fragment(acc[m][n], 0.f);

    load_chunk(0, 0); load_chunk(1, 1);

    for (int i = 0; i < nch; i++) {
        cp_wait1();
        __syncthreads();
        load_chunk(i + 2, (i + 2) % NSTAGE);
        const __nv_bfloat16* sb = (const __nv_bfloat16*)(smem + (size_t)(i % NSTAGE) * STG);
        const __nv_bfloat16* sAh_ = sb;
        const __nv_bfloat16* sAl_ = sb + 2560;
        const __nv_bfloat16* sBh_ = sb + 5120;
        const __nv_bfloat16* sBl_ = sb + 10240;
        #pragma unroll
        for (int kk = 0; kk < 2; kk++) {
            wmma::fragment<wmma::matrix_a, 16, 16, 16, __nv_bfloat16, wmma::row_major> fah[2], fal[2];
            wmma::fragment<wmma::matrix_b, 16, 16, 16, __nv_bfloat16, wmma::col_major> fbh[4], fbl[4];
            #pragma unroll
            for (int m = 0; m < 2; m++) {
                wmma::load_matrix_sync(fah[m], sAh_ + (wr*32 + m*16)*40 + kk*16, 40);
                wmma::load_matrix_sync(fal[m], sAl_ + (wr*32 + m*16)*40 + kk*16, 40);
            }
            #pragma unroll
            for (int n = 0; n < 4; n++) {
                wmma::load_matrix_sync(fbh[n], sBh_ + (wc*64 + n*16)*40 + kk*16, 40);
                wmma::load_matrix_sync(fbl[n], sBl_ + (wc*64 + n*16)*40 + kk*16, 40);
            }
            #pragma unroll
            for (int m = 0; m < 2; m++)
                #pragma unroll
                for (int n = 0; n < 4; n++) {
                    wmma::mma_sync(acc[m][n], fah[m], fbh[n], acc[m][n]);
                    wmma::mma_sync(acc[m][n], fal[m], fbh[n], acc[m][n]);
                    wmma::mma_sync(acc[m][n], fah[m], fbl[n], acc[m][n]);
                }
        }
    }

    if (mode == 0) {
        float* dst = Z + (size_t)rbA * FH + rbB;
        #pragma unroll
        for (int m = 0; m < 2; m++)
            #pragma unroll
            for (int n = 0; n < 4; n++)
                wmma::store_matrix_sync(dst + (size_t)(wr*32 + m*16) * FH + wc*64 + n*16,
                                        acc[m][n], FH, wmma::mem_row_major);
        return;
    }

    __syncthreads();
    float* Zs = (float*)smem;
    #pragma unroll
    for (int m = 0; m < 2; m++)
        #pragma unroll
        for (int n = 0; n < 4; n++)
            wmma::store_matrix_sync(Zs + (wr*32 + m*16) * LDS_EP + wc*64 + n*16,
                                    acc[m][n], LDS_EP, wmma::mem_row_major);
    __syncthreads();

    const int rl = tid >> 1, half = tid & 1;
    const int p = rbA + rl;
    const int n0 = rbB + half * 64;
    const int jb = n0 >> 2;
    const float* zs = Zs + rl * LDS_EP + half * 64;
    const float4* zg = (const float4*)(Z + (size_t)p * FH + n0);
    const float4* bi4 = (const float4*)(biasI + n0);
    float* crow = cst + (size_t)p * HH + jb;
    const bool gath = (hidden != nullptr) && (d_seqP[p] - 1 == step);
    float* hidrow = gath ? (hidden + (size_t)d_orig[p] * HH + jb) : nullptr;

    float cold[16];
    #pragma unroll
    for (int q = 0; q < 4; q++) {
        float4 cv = ld_cg_f4(crow + q*4);
        cold[q*4+0] = cv.x; cold[q*4+1] = cv.y; cold[q*4+2] = cv.z; cold[q*4+3] = cv.w;
    }
    float cn[16]; __nv_bfloat16 hb[16], lb[16];
    #pragma unroll
    for (int g = 0; g < 16; g++) {
        float4 zv = zg[g], bv = bi4[g];
        float vi = zs[g*4+0] + zv.x + bv.x;
        float vf = zs[g*4+1] + zv.y + bv.y;
        float vg = zs[g*4+2] + zv.z + bv.z;
        float vo = zs[g*4+3] + zv.w + bv.w;
        float ig = 1.f / (1.f + __expf(-vi));
        float fg = 1.f / (1.f + __expf(-vf));
        float gg = tanhf(vg);
        float og = 1.f / (1.f + __expf(-vo));
        float c_ = fg * cold[g] + ig * gg;
        cn[g] = c_;
        float hv = og * tanhf(c_);
        __nv_bfloat16 hi_ = __float2bfloat16(hv);
        hb[g] = hi_;
        lb[g] = __float2bfloat16(hv - __bfloat162float(hi_));
        if (gath) hidrow[g] = hv;
    }
    #pragma unroll
    for (int q = 0; q < 4; q++)
        st_cg_f4(crow + q*4, make_float4(cn[q*4], cn[q*4+1], cn[q*4+2], cn[q*4+3]));
    *(uint4*)(hh + (size_t)p * HH + jb)     = ((uint4*)hb)[0];
    *(uint4*)(hh + (size_t)p * HH + jb + 8) = ((uint4*)hb)[1];
    *(uint4*)(hl + (size_t)p * HH + jb)     = ((uint4*)lb)[0];
    *(uint4*)(hl + (size_t)p * HH + jb + 8) = ((uint4*)lb)[1];
}

// ------------- GEMM core, BM=32 (tail half-tiles) -------------
__device__ __forceinline__ void gemm_core32(
    const __nv_bfloat16* __restrict__ Ah, const __nv_bfloat16* __restrict__ Al,
    const __nv_bfloat16* __restrict__ Bh, const __nv_bfloat16* __restrict__ Bl,
    int K, float* __restrict__ Z, int mode,
    const float* __restrict__ biasI, float* __restrict__ cst,
    __nv_bfloat16* __restrict__ hh, __nv_bfloat16* __restrict__ hl,
    float* __restrict__ hidden, int step, int rbA, int rbB, char* smem)
{
    const int tid = threadIdx.x, wid = tid >> 5;
    const int wc = wid;                              // 4 col groups of 32
    const int nch = K >> 5;
    const uint32_t sbase = smem_u32(smem);

    auto load_chunk = [&](int ch, int buf) {
        if (ch < nch) {
            const int k0 = ch << 5;
            const uint32_t st = sbase + (uint32_t)buf * STG32;
            const __nv_bfloat16* sa[2] = {Ah, Al};
            const __nv_bfloat16* sbp[2] = {Bh, Bl};
            #pragma unroll
            for (int op = 0; op < 2; op++) {
                const __nv_bfloat16* src = sa[op] + (size_t)rbA * K + k0;
                uint32_t sb = st + op * 2560u;
                int r = tid >> 2, c = tid & 3;       // 32 rows x 4 groups
                cp16(sb + r * 80 + c * 16, src + (size_t)r * K + c * 8);
            }
            #pragma unroll
            for (int op = 0; op < 2; op++) {
                const __nv_bfloat16* src = sbp[op] + (size_t)rbB * K + k0;
                uint32_t sb = st + 5120u + op * BBYTES;
                #pragma unroll
                for (int it = 0; it < 4; it++) {
                    int ck = it * 128 + tid;
                    int r = ck >> 2, c = ck & 3;
                    cp16(sb + r * 80 + c * 16, src + (size_t)r * K + c * 8);
                }
            }
        }
        cp_commit();
    };

    wmma::fragment<wmma::accumulator, 16, 16, 16, float> acc[2][2];
    #pragma unroll
    for (int m = 0; m < 2; m++)
        #pragma unroll
        for (int n = 0; n < 2; n++) wmma::fill_fragment(acc[m][n], 0.f);

    load_chunk(0, 0); load_chunk(1, 1);

    for (int i = 0; i < nch; i++) {
        cp_wait1();
        __syncthreads();
        load_chunk(i + 2, (i + 2) % NSTAGE);
        const __nv_bfloat16* sb = (const __nv_bfloat16*)(smem + (size_t)(i % NSTAGE) * STG32);
        const __nv_bfloat16* sAh_ = sb;
        const __nv_bfloat16* sAl_ = sb + 1280;
        const __nv_bfloat16* sBh_ = sb + 2560;
        const __nv_bfloat16* sBl_ = sb + 7680;
        #pragma unroll
        for (int kk = 0; kk < 2; kk++) {
            wmma::fragment<wmma::matrix_a, 16, 16, 16, __nv_bfloat16, wmma::row_major> fah[2], fal[2];
            wmma::fragment<wmma::matrix_b, 16, 16, 16, __nv_bfloat16, wmma::col_major> fbh[2], fbl[2];
            #pragma unroll
            for (int m = 0; m < 2; m++) {
                wmma::load_matrix_sync(fah[m], sAh_ + (m*16)*40 + kk*16, 40);
                wmma::load_matrix_sync(fal[m], sAl_ + (m*16)*40 + kk*16, 40);
            }
            #pragma unroll
            for (int n = 0; n < 2; n++) {
                wmma::load_matrix_sync(fbh[n], sBh_ + (wc*32 + n*16)*40 + kk*16, 40);
                wmma::load_matrix_sync(fbl[n], sBl_ + (wc*32 + n*16)*40 + kk*16, 40);
            }
            #pragma unroll
            for (int m = 0; m < 2; m++)
                #pragma unroll
                for (int n = 0; n < 2; n++) {
                    wmma::mma_sync(acc[m][n], fah[m], fbh[n], acc[m][n]);
                    wmma::mma_sync(acc[m][n], fal[m], fbh[n], acc[m][n]);
                    wmma::mma_sync(acc[m][n], fah[m], fbl[n], acc[m][n]);
                }
        }
    }

    if (mode == 0) {
        float* dst = Z + (size_t)rbA * FH + rbB;
        #pragma unroll
        for (int m = 0; m < 2; m++)
            #pragma unroll
            for (int n = 0; n < 2; n++)
                wmma::store_matrix_sync(dst + (size_t)(m*16) * FH + wc*32 + n*16,
                                        acc[m][n], FH, wmma::mem_row_major);
        return;
    }

    __syncthreads();
    float* Zs = (float*)smem;
    #pragma unroll
    for (int m = 0; m < 2; m++)
        #pragma unroll
        for (int n = 0; n < 2; n++)
            wmma::store_matrix_sync(Zs + (m*16) * LDS_EP + wc*32 + n*16,
                                    acc[m][n], LDS_EP, wmma::mem_row_major);
    __syncthreads();

    const int rl = tid >> 2, q4 = tid & 3;           // 32 rows x 4 col quarters
    const int p = rbA + rl;
    const int n0 = rbB + q4 * 32;
    const int jb = n0 >> 2;                          // 8 j's per thread
    const float* zs = Zs + rl * LDS_EP + q4 * 32;
    const float4* zg = (const float4*)(Z + (size_t)p * FH + n0);
    const float4* bi4 = (const float4*)(biasI + n0);
    float* crow = cst + (size_t)p * HH + jb;
    const bool gath = (hidden != nullptr) && (d_seqP[p] - 1 == step);
    float* hidrow = gath ? (hidden + (size_t)d_orig[p] * HH + jb) : nullptr;

    float cold[8];
    #pragma unroll
    for (int q = 0; q < 2; q++) {
        float4 cv = ld_cg_f4(crow + q*4);
        cold[q*4+0] = cv.x; cold[q*4+1] = cv.y; cold[q*4+2] = cv.z; cold[q*4+3] = cv.w;
    }
    float cn[8]; __nv_bfloat16 hb[8], lb[8];
    #pragma unroll
    for (int g = 0; g < 8; g++) {
        float4 zv = zg[g], bv = bi4[g];
        float vi = zs[g*4+0] + zv.x + bv.x;
        float vf = zs[g*4+1] + zv.y + bv.y;
        float vg = zs[g*4+2] + zv.z + bv.z;
        float vo = zs[g*4+3] + zv.w + bv.w;
        float ig = 1.f / (1.f + __expf(-vi));
        float fg = 1.f / (1.f + __expf(-vf));
        float gg = tanhf(vg);
        float og = 1.f / (1.f + __expf(-vo));
        float c_ = fg * cold[g] + ig * gg;
        cn[g] = c_;
        float hv = og * tanhf(c_);
        __nv_bfloat16 hi_ = __float2bfloat16(hv);
        hb[g] = hi_;
        lb[g] = __float2bfloat16(hv - __bfloat162float(hi_));
        if (gath) hidrow[g] = hv;
    }
    #pragma unroll
    for (int q = 0; q < 2; q++)
        st_cg_f4(crow + q*4, make_float4(cn[q*4], cn[q*4+1], cn[q*4+2], cn[q*4+3]));
    *(uint4*)(hh + (size_t)p * HH + jb) = ((uint4*)hb)[0];
    *(uint4*)(hl + (size_t)p * HH + jb) = ((uint4*)lb)[0];
}

// ------------- persistent worker -------------
__device__ __forceinline__ void wait_flag(int idx) {
    volatile int* f = (volatile int*)d_done;
    while (f[idx] < 32) __nanosleep(256);
}

__global__ void __launch_bounds__(128, 2)
worker(const __nv_bfloat16* __restrict__ U1h, const __nv_bfloat16* __restrict__ U1l,
       const __nv_bfloat16* __restrict__ W2h, const __nv_bfloat16* __restrict__ W2l,
       const __nv_bfloat16* __restrict__ U2h, const __nv_bfloat16* __restrict__ U2l,
       const __nv_bfloat16* __restrict__ W1h, const __nv_bfloat16* __restrict__ W1l,
       const __nv_bfloat16* __restrict__ Xh,  const __nv_bfloat16* __restrict__ Xl,
       __nv_bfloat16* __restrict__ H1h, __nv_bfloat16* __restrict__ H1l,
       __nv_bfloat16* __restrict__ H2h, __nv_bfloat16* __restrict__ H2l,
       float* __restrict__ Z1, float* __restrict__ Z2,
       const float* __restrict__ b1i, const float* __restrict__ b2i,
       float* __restrict__ c1, float* __restrict__ c2,
       float* __restrict__ hidden)
{
    extern __shared__ char smem[];
    __shared__ int s_w;
    const int tid = threadIdx.x;
    const size_t HB = (size_t)BB * HH;

    for (;;) {
        __syncthreads();
        if (tid == 0) {
            int k = atomicAdd(&d_ticket, 1);
            s_w = (k < d_ntiles) ? d_tiles[k] : -1;
        }
        __syncthreads();
        const int w = s_w;
        if (w < 0) break;
        const int x = w & 31, y = (w >> 5) & 7, step = (w >> 8) & 127;
        const int role = (w >> 15) & 3, halfT = (w >> 17) & 1;

        if (tid == 0) {
            if (role == 0) {
                if (step > 0) wait_flag(0*TT*8 + (step-1)*8 + y);
                wait_flag(3*TT*8 + step*8 + y);
            } else if (role == 1) {
                wait_flag(0*TT*8 + step*8 + y);
            } else if (role == 2) {
                wait_flag(1*TT*8 + step*8 + y);
                if (step > 0) wait_flag(2*TT*8 + (step-1)*8 + y);
            }
            __threadfence();
        }
        __syncthreads();

        const int rbB = x * BN;
        const __nv_bfloat16 *Ah, *Al, *Bh, *Bl;
        float *Zp, *cs, *hid;
        const float* bi;
        __nv_bfloat16 *oh, *ol;
        int mode, K, rbA;
        if (role == 0) {
            Ah = H1h + (size_t)step * HB; Al = H1l + (size_t)step * HB;
            Bh = U1h; Bl = U1l; K = HH; rbA = y * BM;
            Zp = Z1 + (size_t)step * BB * FH; mode = 1;
            bi = b1i; cs = c1;
            oh = H1h + (size_t)(step+1) * HB; ol = H1l + (size_t)(step+1) * HB;
            hid = nullptr;
        } else if (role == 1) {
            Ah = H1h + (size_t)(step+1) * HB; Al = H1l + (size_t)(step+1) * HB;
            Bh = W2h; Bl = W2l; K = HH; rbA = y * BM;
            Zp = Z2 + (size_t)step * BB * FH; mode = 0;
            bi = nullptr; cs = nullptr; oh = nullptr; ol = nullptr; hid = nullptr;
        } else if (role == 2) {
            Ah = H2h + (size_t)step * HB; Al = H2l + (size_t)step * HB;
            Bh = U2h; Bl = U2l; K = HH; rbA = y * BM;
            Zp = Z2 + (size_t)step * BB * FH; mode = 1;
            bi = b2i; cs = c2;
            oh = H2h + (size_t)(step+1) * HB; ol = H2l + (size_t)(step+1) * HB;
            hid = hidden;
        } else {              // role 3: W1 input-transform slice (x(step) @ W1)
            Ah = Xh; Al = Xl;
            Bh = W1h; Bl = W1l; K = DIN; rbA = step * BB + y * BM;
            Zp = Z1; mode = 0;
            bi = nullptr; cs = nullptr; oh = nullptr; ol = nullptr; hid = nullptr;
        }

        if (halfT)
            gemm_core32(Ah, Al, Bh, Bl, K, Zp, mode, bi, cs, oh, ol, hid, step, rbA, rbB, smem);
        else
            gemm_core(Ah, Al, Bh, Bl, K, Zp, mode, bi, cs, oh, ol, hid, step, rbA, rbB, smem);

        __threadfence();
        __syncthreads();
        if (tid == 0) atomicAdd(&d_done[role*TT*8 + step*8 + y], 1);
    }
}

// ------------- launch -------------
extern "C" void kernel_launch(void* const* d_in, const int* in_sizes, int n_in,
                              void* d_out, int out_size)
{
    const float* chars  = (const float*)d_in[0];
    const int*   seqlen = (const int*)  d_in[1];
    const float* W1 = (const float*)d_in[2];
    const float* U1 = (const float*)d_in[3];
    const float* b1 = (const float*)d_in[4];
    const float* W2 = (const float*)d_in[5];
    const float* U2 = (const float*)d_in[6];
    const float* b2 = (const float*)d_in[7];
    const float* Wd = (const float*)d_in[8];
    const float* bd = (const float*)d_in[9];
    float* out = (float*)d_out;

    cudaFuncSetAttribute(worker, cudaFuncAttributeMaxDynamicSharedMemorySize, SMEM_DYN);

    float *Z1, *Z2, *c1, *c2, *hidden, *b1i, *b2i;
    __nv_bfloat16 *Xh, *Xl, *H1h, *H1l, *H2h, *H2l;
    __nv_bfloat16 *W1h, *W1l, *U1h, *U1l, *W2h, *W2l, *U2h, *U2l;
    cudaGetSymbolAddress((void**)&Z1, d_Z1);   cudaGetSymbolAddress((void**)&Z2, d_Z2);
    cudaGetSymbolAddress((void**)&c1, d_c1);   cudaGetSymbolAddress((void**)&c2, d_c2);
    cudaGetSymbolAddress((void**)&hidden, d_hidden);
    cudaGetSymbolAddress((void**)&b1i, d_b1i); cudaGetSymbolAddress((void**)&b2i, d_b2i);
    cudaGetSymbolAddress((void**)&Xh, d_Xh);   cudaGetSymbolAddress((void**)&Xl, d_Xl);
    cudaGetSymbolAddress((void**)&H1h, d_H1h); cudaGetSymbolAddress((void**)&H1l, d_H1l);
    cudaGetSymbolAddress((void**)&H2h, d_H2h); cudaGetSymbolAddress((void**)&H2l, d_H2l);
    cudaGetSymbolAddress((void**)&W1h, d_W1h); cudaGetSymbolAddress((void**)&W1l, d_W1l);
    cudaGetSymbolAddress((void**)&U1h, d_U1h); cudaGetSymbolAddress((void**)&U1l, d_U1l);
    cudaGetSymbolAddress((void**)&W2h, d_W2h); cudaGetSymbolAddress((void**)&W2l, d_W2l);
    cudaGetSymbolAddress((void**)&U2h, d_U2h); cudaGetSymbolAddress((void**)&U2l, d_U2l);

    split_w<<<(FH*DIN)/256, 256>>>(W1, W1h, W1l, DIN);
    split_w<<<(FH*HH)/256, 256>>>(U1, U1h, U1l, HH);
    split_w<<<(FH*HH)/256, 256>>>(W2, W2h, W2l, HH);
    split_w<<<(FH*HH)/256, 256>>>(U2, U2h, U2l, HH);
    interleave_bias<<<FH/256, 256>>>(b1, b1i);
    interleave_bias<<<FH/256, 256>>>(b2, b2i);
    seq_sort<<<1, BB>>>(seqlen);
    seq_cnt<<<1, TT+1>>>(seqlen);
    split_chars<<<(TBROWS*64)/256, 256>>>(chars, Xh, Xl);
    init_states<<<(BB*HH)/256, 256>>>();
    build_tiles<<<3, 256>>>();

    // persistent dataflow worker: w1 / l1 / w2 / l2 tiles with flag deps
    worker<<<NWORKER, 128, SMEM_DYN>>>(U1h, U1l, W2h, W2l, U2h, U2l,
                                       W1h, W1l, Xh, Xl,
                                       H1h, H1l, H2h, H2l, Z1, Z2,
                                       b1i, b2i, c1, c2, hidden);

    dense_relu<<<BB, 128>>>(hidden, Wd, bd, out);
}

// round 14
// speedup vs baseline: 3.0968x; 1.3514x over previous
#include <cuda_runtime.h>
#include <cuda_fp16.h>
#include <mma.h>
#include <cstdint>

using namespace nvcuda;

#define BB   512
#define TT   128
#define DIN  256
#define HH   1024
#define FH   4096
#define TBROWS (TT*BB)

#define BM 64
#define BN 128
#define ABYTES 5120u          // 64 rows * 80 B
#define BBYTES 10240u         // 128 rows * 80 B
#define STG 25600u            // BM64 stage: A + 2*B
#define STG32 23040u          // BM32 stage: 2560 + 2*10240
#define NSTAGE 3
#define SMEM_DYN 76800
#define LDS_EP 132
#define NWORKER 296
#define TILE_MAX 131072
#define NSLOT 524             // 4 pre + 130 ticks * 4

// ------------- device scratch (no allocation allowed) -------------
__device__ float d_Z1[(size_t)TBROWS*FH];
__device__ float d_Z2[(size_t)TBROWS*FH];
__device__ float d_c1[BB*HH], d_c2[BB*HH];
__device__ float d_hidden[BB*HH];
__device__ float d_b1i[FH], d_b2i[FH];
__device__ int   d_pos[BB], d_orig[BB], d_seqP[BB], d_cnt[TT+1];
__device__ int   d_tiles[TILE_MAX];
__device__ int   d_ntiles;
__device__ int   d_ticket;
__device__ int   d_done[4*TT*8];
__device__ __half d_Xh[(size_t)TBROWS*DIN];
__device__ __half d_H1h[(size_t)(TT+1)*BB*HH];
__device__ __half d_H2h[(size_t)(TT+1)*BB*HH];
__device__ __half d_W1h[(size_t)FH*DIN], d_W1l[(size_t)FH*DIN];
__device__ __half d_U1h[(size_t)FH*HH],  d_U1l[(size_t)FH*HH];
__device__ __half d_W2h[(size_t)FH*HH],  d_W2l[(size_t)FH*HH];
__device__ __half d_U2h[(size_t)FH*HH],  d_U2l[(size_t)FH*HH];

// ------------- PTX helpers (Ampere-level: valid on plain sm_103) ------
__device__ __forceinline__ uint32_t smem_u32(const void* p) {
    uint32_t a;
    asm("{ .reg .u64 t; cvta.to.shared.u64 t, %1; cvt.u32.u64 %0, t; }" : "=r"(a) : "l"(p));
    return a;
}
__device__ __forceinline__ void cp16(uint32_t d, const void* s) {
    asm volatile("cp.async.cg.shared.global [%0], [%1], 16;" :: "r"(d), "l"(s) : "memory");
}
__device__ __forceinline__ void cp_commit() { asm volatile("cp.async.commit_group;" ::: "memory"); }
__device__ __forceinline__ void cp_wait1()  { asm volatile("cp.async.wait_group 1;" ::: "memory"); }
__device__ __forceinline__ float4 ld_cg_f4(const float* p) {
    float4 v;
    asm volatile("ld.global.cg.v4.f32 {%0,%1,%2,%3}, [%4];"
                 : "=f"(v.x), "=f"(v.y), "=f"(v.z), "=f"(v.w) : "l"(p));
    return v;
}
__device__ __forceinline__ void st_cg_f4(float* p, float4 v) {
    asm volatile("st.global.cg.v4.f32 [%0], {%1,%2,%3,%4};"
                 :: "l"(p), "f"(v.x), "f"(v.y), "f"(v.z), "f"(v.w) : "memory");
}

// ------------- preprocessing -------------
// W [K, 4H] -> Wt[n=j*4+gate][k], split hi/lo fp16 (22-bit effective weights)
__global__ void split_w(const float* __restrict__ W, __half* __restrict__ oh,
                        __half* __restrict__ ol, int K)
{
    size_t i = (size_t)blockIdx.x * blockDim.x + threadIdx.x;
    int k = (int)(i % K), n = (int)(i / K);
    float x = W[(size_t)k * FH + (n & 3) * HH + (n >> 2)];
    __half h = __float2half(x);
    oh[i] = h;
    ol[i] = __float2half(x - __half2float(h));
}
__global__ void interleave_bias(const float* __restrict__ b, float* __restrict__ bi)
{
    int n = blockIdx.x * blockDim.x + threadIdx.x;
    bi[n] = b[(n & 3) * HH + (n >> 2)];
}
__global__ void seq_sort(const int* __restrict__ seqlen)
{
    int b = threadIdx.x;
    int s = seqlen[b];
    int pos = 0;
    for (int j = 0; j < BB; j++) {
        int sj = seqlen[j];
        pos += (sj > s) || (sj == s && j < b);
    }
    d_pos[b] = pos;
    d_orig[pos] = b;
    d_seqP[pos] = s;
}
__global__ void seq_cnt(const int* __restrict__ seqlen)
{
    int t = threadIdx.x;
    if (t > TT) return;
    int c = 0;
    for (int j = 0; j < BB; j++) c += (seqlen[j] >= t + 1);
    d_cnt[t] = c;
}
// chars [B][T][256] -> fp16 time-major PERMUTED [t*512 + pos[b]][256]
__global__ void split_chars(const float* __restrict__ chars, __half* __restrict__ xh)
{
    int idx = blockIdx.x * blockDim.x + threadIdx.x;
    int d4 = idx & 63, rest = idx >> 6;
    int b = rest & (BB - 1), t = rest >> 9;
    float4 v = *(const float4*)(chars + ((size_t)b * TT + t) * DIN + d4 * 4);
    size_t o = ((size_t)t * BB + d_pos[b]) * DIN + d4 * 4;
    xh[o + 0] = __float2half(v.x);
    xh[o + 1] = __float2half(v.y);
    xh[o + 2] = __float2half(v.z);
    xh[o + 3] = __float2half(v.w);
}
__global__ void init_states()
{
    int i = blockIdx.x * blockDim.x + threadIdx.x;  // BB*HH threads
    d_c1[i] = 0.f; d_c2[i] = 0.f;
    __half z = __float2half(0.f);
    d_H1h[i] = z; d_H2h[i] = z;
    if (i < 4*TT*8) d_done[i] = 0;
    if (i == 0) d_ticket = 0;
}

// slot -> (role, step). roles: 0=l1, 1=w2, 2=l2, 3=w1. -1 if invalid.
__device__ __forceinline__ int slot_decode(int j, int* role)
{
    if (j < 4) { *role = 3; return j; }
    int t = (j - 4) >> 2, q = (j - 4) & 3;
    int r, s;
    if (q == 0)      { r = 3; s = t + 4; }
    else if (q == 1) { r = 0; s = t; }
    else if (q == 2) { r = 1; s = t - 1; }
    else             { r = 2; s = t - 2; }
    *role = r;
    return (s >= 0 && s < TT) ? s : -1;
}
__global__ void build_tiles()
{
    int id = blockIdx.x * blockDim.x + threadIdx.x;
    if (id >= NSLOT) return;
    int off = 0;
    for (int j = 0; j < id; j++) {
        int r, s = slot_decode(j, &r);
        if (s >= 0) off += ((d_cnt[s] + 63) >> 6) * 32;
    }
    if (id == 0) {
        int tot = 0;
        for (int j = 0; j < NSLOT; j++) {
            int r, s = slot_decode(j, &r);
            if (s >= 0) tot += ((d_cnt[s] + 63) >> 6) * 32;
        }
        d_ntiles = tot;
    }
    int role, step = slot_decode(id, &role);
    if (step < 0) return;
    int c = d_cnt[step];
    int ny = (c + 63) >> 6;
    for (int y = 0; y < ny; y++) {
        int half = (c <= y * 64 + 32) ? 1 : 0;
        for (int x = 0; x < 32; x++)
            d_tiles[off++] = x | (y << 5) | (step << 8) | (role << 15) | (half << 17);
    }
}
__global__ void dense_relu(const float* __restrict__ hidden, const float* __restrict__ Wd,
                           const float* __restrict__ bd, float* __restrict__ out)
{
    __shared__ float buf[3][128];
    int b = blockIdx.x, tid = threadIdx.x;
    const float* hb = hidden + (size_t)b * HH;
    float s0 = 0.f, s1 = 0.f, s2 = 0.f;
    for (int k = tid; k < HH; k += 128) {
        float hv = hb[k];
        s0 = fmaf(hv, Wd[k*3+0], s0); s1 = fmaf(hv, Wd[k*3+1], s1); s2 = fmaf(hv, Wd[k*3+2], s2);
    }
    buf[0][tid] = s0; buf[1][tid] = s1; buf[2][tid] = s2;
    __syncthreads();
    for (int s = 64; s > 0; s >>= 1) {
        if (tid < s) { buf[0][tid]+=buf[0][tid+s]; buf[1][tid]+=buf[1][tid+s]; buf[2][tid]+=buf[2][tid+s]; }
        __syncthreads();
    }
    if (tid < 3) out[b*3 + tid] = fmaxf(buf[tid][0] + bd[tid], 0.f);
}

// ------------- GEMM core, BM=64 -------------
// D[64,128] = A16[64,K] @ (Bh + Bl)[128,K]^T  (2 MMA terms: A@Bh + A@Bl)
// mode 0: Z[rowA,n] = D.  mode 1: z = D + Z + bias -> gates -> c, h(fp16).
__device__ __forceinline__ void gemm_core(
    const __half* __restrict__ Ah,
    const __half* __restrict__ Bh, const __half* __restrict__ Bl,
    int K, float* __restrict__ Z, int mode,
    const float* __restrict__ biasI, float* __restrict__ cst,
    __half* __restrict__ hh,
    float* __restrict__ hidden, int step, int rbA, int rbB, char* smem)
{
    const int tid = threadIdx.x, wid = tid >> 5;
    const int wr = wid & 1, wc = wid >> 1;
    const int nch = K >> 5;
    const uint32_t sbase = smem_u32(smem);

    auto load_chunk = [&](int ch, int buf) {
        if (ch < nch) {
            const int k0 = ch << 5;
            const uint32_t st = sbase + (uint32_t)buf * STG;
            {
                const __half* src = Ah + (size_t)rbA * K + k0;
                #pragma unroll
                for (int it = 0; it < 2; it++) {
                    int ck = it * 128 + tid;
                    int r = ck >> 2, c = ck & 3;
                    cp16(st + r * 80 + c * 16, src + (size_t)r * K + c * 8);
                }
            }
            const __half* sbp[2] = {Bh, Bl};
            #pragma unroll
            for (int op = 0; op < 2; op++) {
                const __half* src = sbp[op] + (size_t)rbB * K + k0;
                uint32_t sb = st + ABYTES + op * BBYTES;
                #pragma unroll
                for (int it = 0; it < 4; it++) {
                    int ck = it * 128 + tid;
                    int r = ck >> 2, c = ck & 3;
                    cp16(sb + r * 80 + c * 16, src + (size_t)r * K + c * 8);
                }
            }
        }
        cp_commit();
    };

    wmma::fragment<wmma::accumulator, 16, 16, 16, float> acc[2][4];
    #pragma unroll
    for (int m = 0; m < 2; m++)
        #pragma unroll
        for (int n = 0; n < 4; n++) wmma::fill_fragment(acc[m][n], 0.f);

    load_chunk(0, 0); load_chunk(1, 1);

    for (int i = 0; i < nch; i++) {
        cp_wait1();
        __syncthreads();
        load_chunk(i + 2, (i + 2) % NSTAGE);
        const __half* sb = (const __half*)(smem + (size_t)(i % NSTAGE) * STG);
        const __half* sAh_ = sb;
        const __half* sBh_ = sb + 2560;
        const __half* sBl_ = sb + 7680;
        #pragma unroll
        for (int kk = 0; kk < 2; kk++) {
            wmma::fragment<wmma::matrix_a, 16, 16, 16, __half, wmma::row_major> fah[2];
            wmma::fragment<wmma::matrix_b, 16, 16, 16, __half, wmma::col_major> fbh[4], fbl[4];
            #pragma unroll
            for (int m = 0; m < 2; m++)
                wmma::load_matrix_sync(fah[m], sAh_ + (wr*32 + m*16)*40 + kk*16, 40);
            #pragma unroll
            for (int n = 0; n < 4; n++) {
                wmma::load_matrix_sync(fbh[n], sBh_ + (wc*64 + n*16)*40 + kk*16, 40);
                wmma::load_matrix_sync(fbl[n], sBl_ + (wc*64 + n*16)*40 + kk*16, 40);
            }
            #pragma unroll
            for (int m = 0; m < 2; m++)
                #pragma unroll
                for (int n = 0; n < 4; n++) {
                    wmma::mma_sync(acc[m][n], fah[m], fbh[n], acc[m][n]);
                    wmma::mma_sync(acc[m][n], fah[m], fbl[n], acc[m][n]);
                }
        }
    }

    if (mode == 0) {
        float* dst = Z + (size_t)rbA * FH + rbB;
        #pragma unroll
        for (int m = 0; m < 2; m++)
            #pragma unroll
            for (int n = 0; n < 4; n++)
                wmma::store_matrix_sync(dst + (size_t)(wr*32 + m*16) * FH + wc*64 + n*16,
                                        acc[m][n], FH, wmma::mem_row_major);
        return;
    }

    __syncthreads();
    float* Zs = (float*)smem;
    #pragma unroll
    for (int m = 0; m < 2; m++)
        #pragma unroll
        for (int n = 0; n < 4; n++)
            wmma::store_matrix_sync(Zs + (wr*32 + m*16) * LDS_EP + wc*64 + n*16,
                                    acc[m][n], LDS_EP, wmma::mem_row_major);
    __syncthreads();

    const int rl = tid >> 1, half = tid & 1;
    const int p = rbA + rl;
    const int n0 = rbB + half * 64;
    const int jb = n0 >> 2;
    const float* zs = Zs + rl * LDS_EP + half * 64;
    const float4* zg = (const float4*)(Z + (size_t)p * FH + n0);
    const float4* bi4 = (const float4*)(biasI + n0);
    float* crow = cst + (size_t)p * HH + jb;
    const bool gath = (hidden != nullptr) && (d_seqP[p] - 1 == step);
    float* hidrow = gath ? (hidden + (size_t)d_orig[p] * HH + jb) : nullptr;

    float cold[16];
    #pragma unroll
    for (int q = 0; q < 4; q++) {
        float4 cv = ld_cg_f4(crow + q*4);
        cold[q*4+0] = cv.x; cold[q*4+1] = cv.y; cold[q*4+2] = cv.z; cold[q*4+3] = cv.w;
    }
    float cn[16]; __half hb[16];
    #pragma unroll
    for (int g = 0; g < 16; g++) {
        float4 zv = zg[g], bv = bi4[g];
        float vi = zs[g*4+0] + zv.x + bv.x;
        float vf = zs[g*4+1] + zv.y + bv.y;
        float vg = zs[g*4+2] + zv.z + bv.z;
        float vo = zs[g*4+3] + zv.w + bv.w;
        float ig = 1.f / (1.f + __expf(-vi));
        float fg = 1.f / (1.f + __expf(-vf));
        float gg = tanhf(vg);
        float og = 1.f / (1.f + __expf(-vo));
        float c_ = fg * cold[g] + ig * gg;
        cn[g] = c_;
        float hv = og * tanhf(c_);
        hb[g] = __float2half(hv);
        if (gath) hidrow[g] = hv;
    }
    #pragma unroll
    for (int q = 0; q < 4; q++)
        st_cg_f4(crow + q*4, make_float4(cn[q*4], cn[q*4+1], cn[q*4+2], cn[q*4+3]));
    *(uint4*)(hh + (size_t)p * HH + jb)     = ((uint4*)hb)[0];
    *(uint4*)(hh + (size_t)p * HH + jb + 8) = ((uint4*)hb)[1];
}

// ------------- GEMM core, BM=32 (tail half-tiles) -------------
__device__ __forceinline__ void gemm_core32(
    const __half* __restrict__ Ah,
    const __half* __restrict__ Bh, const __half* __restrict__ Bl,
    int K, float* __restrict__ Z, int mode,
    const float* __restrict__ biasI, float* __restrict__ cst,
    __half* __restrict__ hh,
    float* __restrict__ hidden, int step, int rbA, int rbB, char* smem)
{
    const int tid = threadIdx.x, wid = tid >> 5;
    const int wc = wid;
    const int nch = K >> 5;
    const uint32_t sbase = smem_u32(smem);

    auto load_chunk = [&](int ch, int buf) {
        if (ch < nch) {
            const int k0 = ch << 5;
            const uint32_t st = sbase + (uint32_t)buf * STG32;
            {
                const __half* src = Ah + (size_t)rbA * K + k0;
                int r = tid >> 2, c = tid & 3;
                cp16(st + r * 80 + c * 16, src + (size_t)r * K + c * 8);
            }
            const __half* sbp[2] = {Bh, Bl};
            #pragma unroll
            for (int op = 0; op < 2; op++) {
                const __half* src = sbp[op] + (size_t)rbB * K + k0;
                uint32_t sb = st + 2560u + op * BBYTES;
                #pragma unroll
                for (int it = 0; it < 4; it++) {
                    int ck = it * 128 + tid;
                    int r = ck >> 2, c = ck & 3;
                    cp16(sb + r * 80 + c * 16, src + (size_t)r * K + c * 8);
                }
            }
        }
        cp_commit();
    };

    wmma::fragment<wmma::accumulator, 16, 16, 16, float> acc[2][2];
    #pragma unroll
    for (int m = 0; m < 2; m++)
        #pragma unroll
        for (int n = 0; n < 2; n++) wmma::fill_fragment(acc[m][n], 0.f);

    load_chunk(0, 0); load_chunk(1, 1);

    for (int i = 0; i < nch; i++) {
        cp_wait1();
        __syncthreads();
        load_chunk(i + 2, (i + 2) % NSTAGE);
        const __half* sb = (const __half*)(smem + (size_t)(i % NSTAGE) * STG32);
        const __half* sAh_ = sb;
        const __half* sBh_ = sb + 1280;
        const __half* sBl_ = sb + 6400;
        #pragma unroll
        for (int kk = 0; kk < 2; kk++) {
            wmma::fragment<wmma::matrix_a, 16, 16, 16, __half, wmma::row_major> fah[2];
            wmma::fragment<wmma::matrix_b, 16, 16, 16, __half, wmma::col_major> fbh[2], fbl[2];
            #pragma unroll
            for (int m = 0; m < 2; m++)
                wmma::load_matrix_sync(fah[m], sAh_ + (m*16)*40 + kk*16, 40);
            #pragma unroll
            for (int n = 0; n < 2; n++) {
                wmma::load_matrix_sync(fbh[n], sBh_ + (wc*32 + n*16)*40 + kk*16, 40);
                wmma::load_matrix_sync(fbl[n], sBl_ + (wc*32 + n*16)*40 + kk*16, 40);
            }
            #pragma unroll
            for (int m = 0; m < 2; m++)
                #pragma unroll
                for (int n = 0; n < 2; n++) {
                    wmma::mma_sync(acc[m][n], fah[m], fbh[n], acc[m][n]);
                    wmma::mma_sync(acc[m][n], fah[m], fbl[n], acc[m][n]);
                }
        }
    }

    if (mode == 0) {
        float* dst = Z + (size_t)rbA * FH + rbB;
        #pragma unroll
        for (int m = 0; m < 2; m++)
            #pragma unroll
            for (int n = 0; n < 2; n++)
                wmma::store_matrix_sync(dst + (size_t)(m*16) * FH + wc*32 + n*16,
                                        acc[m][n], FH, wmma::mem_row_major);
        return;
    }

    __syncthreads();
    float* Zs = (float*)smem;
    #pragma unroll
    for (int m = 0; m < 2; m++)
        #pragma unroll
        for (int n = 0; n < 2; n++)
            wmma::store_matrix_sync(Zs + (m*16) * LDS_EP + wc*32 + n*16,
                                    acc[m][n], LDS_EP, wmma::mem_row_major);
    __syncthreads();

    const int rl = tid >> 2, q4 = tid & 3;
    const int p = rbA + rl;
    const int n0 = rbB + q4 * 32;
    const int jb = n0 >> 2;
    const float* zs = Zs + rl * LDS_EP + q4 * 32;
    const float4* zg = (const float4*)(Z + (size_t)p * FH + n0);
    const float4* bi4 = (const float4*)(biasI + n0);
    float* crow = cst + (size_t)p * HH + jb;
    const bool gath = (hidden != nullptr) && (d_seqP[p] - 1 == step);
    float* hidrow = gath ? (hidden + (size_t)d_orig[p] * HH + jb) : nullptr;

    float cold[8];
    #pragma unroll
    for (int q = 0; q < 2; q++) {
        float4 cv = ld_cg_f4(crow + q*4);
        cold[q*4+0] = cv.x; cold[q*4+1] = cv.y; cold[q*4+2] = cv.z; cold[q*4+3] = cv.w;
    }
    float cn[8]; __half hb[8];
    #pragma unroll
    for (int g = 0; g < 8; g++) {
        float4 zv = zg[g], bv = bi4[g];
        float vi = zs[g*4+0] + zv.x + bv.x;
        float vf = zs[g*4+1] + zv.y + bv.y;
        float vg = zs[g*4+2] + zv.z + bv.z;
        float vo = zs[g*4+3] + zv.w + bv.w;
        float ig = 1.f / (1.f + __expf(-vi));
        float fg = 1.f / (1.f + __expf(-vf));
        float gg = tanhf(vg);
        float og = 1.f / (1.f + __expf(-vo));
        float c_ = fg * cold[g] + ig * gg;
        cn[g] = c_;
        float hv = og * tanhf(c_);
        hb[g] = __float2half(hv);
        if (gath) hidrow[g] = hv;
    }
    #pragma unroll
    for (int q = 0; q < 2; q++)
        st_cg_f4(crow + q*4, make_float4(cn[q*4], cn[q*4+1], cn[q*4+2], cn[q*4+3]));
    *(uint4*)(hh + (size_t)p * HH + jb) = ((uint4*)hb)[0];
}

// ------------- persistent worker -------------
__device__ __forceinline__ void wait_flag(int idx) {
    volatile int* f = (volatile int*)d_done;
    while (f[idx] < 32) __nanosleep(256);
}

__global__ void __launch_bounds__(128, 2)
worker(const __half* __restrict__ U1h, const __half* __restrict__ U1l,
       const __half* __restrict__ W2h, const __half* __restrict__ W2l,
       const __half* __restrict__ U2h, const __half* __restrict__ U2l,
       const __half* __restrict__ W1h, const __half* __restrict__ W1l,
       const __half* __restrict__ Xh,
       __half* __restrict__ H1h, __half* __restrict__ H2h,
       float* __restrict__ Z1, float* __restrict__ Z2,
       const float* __restrict__ b1i, const float* __restrict__ b2i,
       float* __restrict__ c1, float* __restrict__ c2,
       float* __restrict__ hidden)
{
    extern __shared__ char smem[];
    __shared__ int s_w;
    const int tid = threadIdx.x;
    const size_t HB = (size_t)BB * HH;

    for (;;) {
        __syncthreads();
        if (tid == 0) {
            int k = atomicAdd(&d_ticket, 1);
            s_w = (k < d_ntiles) ? d_tiles[k] : -1;
        }
        __syncthreads();
        const int w = s_w;
        if (w < 0) break;
        const int x = w & 31, y = (w >> 5) & 7, step = (w >> 8) & 127;
        const int role = (w >> 15) & 3, halfT = (w >> 17) & 1;

        if (tid == 0) {
            if (role == 0) {
                if (step > 0) wait_flag(0*TT*8 + (step-1)*8 + y);
                wait_flag(3*TT*8 + step*8 + y);
            } else if (role == 1) {
                wait_flag(0*TT*8 + step*8 + y);
            } else if (role == 2) {
                wait_flag(1*TT*8 + step*8 + y);
                if (step > 0) wait_flag(2*TT*8 + (step-1)*8 + y);
            }
            __threadfence();
        }
        __syncthreads();

        const int rbB = x * BN;
        const __half *Ah, *Bh, *Bl;
        float *Zp, *cs, *hid;
        const float* bi;
        __half *oh;
        int mode, K, rbA;
        if (role == 0) {
            Ah = H1h + (size_t)step * HB;
            Bh = U1h; Bl = U1l; K = HH; rbA = y * BM;
            Zp = Z1 + (size_t)step * BB * FH; mode = 1;
            bi = b1i; cs = c1;
            oh = H1h + (size_t)(step+1) * HB;
            hid = nullptr;
        } else if (role == 1) {
            Ah = H1h + (size_t)(step+1) * HB;
            Bh = W2h; Bl = W2l; K = HH; rbA = y * BM;
            Zp = Z2 + (size_t)step * BB * FH; mode = 0;
            bi = nullptr; cs = nullptr; oh = nullptr; hid = nullptr;
        } else if (role == 2) {
            Ah = H2h + (size_t)step * HB;
            Bh = U2h; Bl = U2l; K = HH; rbA = y * BM;
            Zp = Z2 + (size_t)step * BB * FH; mode = 1;
            bi = b2i; cs = c2;
            oh = H2h + (size_t)(step+1) * HB;
            hid = hidden;
        } else {              // role 3: W1 input-transform slice (x(step) @ W1)
            Ah = Xh;
            Bh = W1h; Bl = W1l; K = DIN; rbA = step * BB + y * BM;
            Zp = Z1; mode = 0;
            bi = nullptr; cs = nullptr; oh = nullptr; hid = nullptr;
        }

        if (halfT)
            gemm_core32(Ah, Bh, Bl, K, Zp, mode, bi, cs, oh, hid, step, rbA, rbB, smem);
        else
            gemm_core(Ah, Bh, Bl, K, Zp, mode, bi, cs, oh, hid, step, rbA, rbB, smem);

        __threadfence();
        __syncthreads();
        if (tid == 0) atomicAdd(&d_done[role*TT*8 + step*8 + y], 1);
    }
}

// ------------- launch -------------
extern "C" void kernel_launch(void* const* d_in, const int* in_sizes, int n_in,
                              void* d_out, int out_size)
{
    const float* chars  = (const float*)d_in[0];
    const int*   seqlen = (const int*)  d_in[1];
    const float* W1 = (const float*)d_in[2];
    const float* U1 = (const float*)d_in[3];
    const float* b1 = (const float*)d_in[4];
    const float* W2 = (const float*)d_in[5];
    const float* U2 = (const float*)d_in[6];
    const float* b2 = (const float*)d_in[7];
    const float* Wd = (const float*)d_in[8];
    const float* bd = (const float*)d_in[9];
    float* out = (float*)d_out;

    cudaFuncSetAttribute(worker, cudaFuncAttributeMaxDynamicSharedMemorySize, SMEM_DYN);

    float *Z1, *Z2, *c1, *c2, *hidden, *b1i, *b2i;
    __half *Xh, *H1h, *H2h;
    __half *W1h, *W1l, *U1h, *U1l, *W2h, *W2l, *U2h, *U2l;
    cudaGetSymbolAddress((void**)&Z1, d_Z1);   cudaGetSymbolAddress((void**)&Z2, d_Z2);
    cudaGetSymbolAddress((void**)&c1, d_c1);   cudaGetSymbolAddress((void**)&c2, d_c2);
    cudaGetSymbolAddress((void**)&hidden, d_hidden);
    cudaGetSymbolAddress((void**)&b1i, d_b1i); cudaGetSymbolAddress((void**)&b2i, d_b2i);
    cudaGetSymbolAddress((void**)&Xh, d_Xh);
    cudaGetSymbolAddress((void**)&H1h, d_H1h);
    cudaGetSymbolAddress((void**)&H2h, d_H2h);
    cudaGetSymbolAddress((void**)&W1h, d_W1h); cudaGetSymbolAddress((void**)&W1l, d_W1l);
    cudaGetSymbolAddress((void**)&U1h, d_U1h); cudaGetSymbolAddress((void**)&U1l, d_U1l);
    cudaGetSymbolAddress((void**)&W2h, d_W2h); cudaGetSymbolAddress((void**)&W2l, d_W2l);
    cudaGetSymbolAddress((void**)&U2h, d_U2h); cudaGetSymbolAddress((void**)&U2l, d_U2l);

    split_w<<<(FH*DIN)/256, 256>>>(W1, W1h, W1l, DIN);
    split_w<<<(FH*HH)/256, 256>>>(U1, U1h, U1l, HH);
    split_w<<<(FH*HH)/256, 256>>>(W2, W2h, W2l, HH);
    split_w<<<(FH*HH)/256, 256>>>(U2, U2h, U2l, HH);
    interleave_bias<<<FH/256, 256>>>(b1, b1i);
    interleave_bias<<<FH/256, 256>>>(b2, b2i);
    seq_sort<<<1, BB>>>(seqlen);
    seq_cnt<<<1, TT+1>>>(seqlen);
    split_chars<<<(TBROWS*64)/256, 256>>>(chars, Xh);
    init_states<<<(BB*HH)/256, 256>>>();
    build_tiles<<<3, 256>>>();

    worker<<<NWORKER, 128, SMEM_DYN>>>(U1h, U1l, W2h, W2l, U2h, U2l,
                                       W1h, W1l, Xh,
                                       H1h, H2h, Z1, Z2,
                                       b1i, b2i, c1, c2, hidden);

    dense_relu<<<BB, 128>>>(hidden, Wd, bd, out);
}

// round 15
// speedup vs baseline: 3.4026x; 1.0987x over previous
#include <cuda_runtime.h>
#include <cuda_fp16.h>
#include <mma.h>
#include <cstdint>

using namespace nvcuda;

#define BB   512
#define TT   128
#define DIN  256
#define HH   1024
#define FH   4096
#define TBROWS (TT*BB)

#define BM 64
#define BN 128
#define ABYTES 5120u          // 64 rows * 80 B
#define BBYTES 10240u         // 128 rows * 80 B
#define NSTAGE 3
#define SMEM_DYN 76800        // 3 * (5120 + 2*10240)
#define LDS_EP 132
#define NWORKER 296
#define TILE_MAX 131072
#define NSLOT 524             // 4 pre + 130 ticks * 4

// ------------- device scratch (no allocation allowed) -------------
__device__ float d_Z1[(size_t)TBROWS*FH];
__device__ float d_Z2[(size_t)TBROWS*FH];
__device__ float d_c1[BB*HH], d_c2[BB*HH];
__device__ float d_hidden[BB*HH];
__device__ float d_b1i[FH], d_b2i[FH];
__device__ int   d_pos[BB], d_orig[BB], d_seqP[BB], d_cnt[TT+1];
__device__ int   d_tiles[TILE_MAX];
__device__ int   d_ntiles;
__device__ int   d_ticket;
__device__ int   d_done[4*TT*8];
__device__ __half d_Xh[(size_t)TBROWS*DIN];
__device__ __half d_H1h[(size_t)(TT+1)*BB*HH];
__device__ __half d_H2h[(size_t)(TT+1)*BB*HH];
__device__ __half d_W1h[(size_t)FH*DIN];                      // 1-term
__device__ __half d_U1h[(size_t)FH*HH],  d_U1l[(size_t)FH*HH]; // 2-term
__device__ __half d_W2h[(size_t)FH*HH];                        // 1-term
__device__ __half d_U2h[(size_t)FH*HH],  d_U2l[(size_t)FH*HH]; // 2-term

// ------------- PTX helpers (Ampere-level: valid on plain sm_103) ------
__device__ __forceinline__ uint32_t smem_u32(const void* p) {
    uint32_t a;
    asm("{ .reg .u64 t; cvta.to.shared.u64 t, %1; cvt.u32.u64 %0, t; }" : "=r"(a) : "l"(p));
    return a;
}
__device__ __forceinline__ void cp16(uint32_t d, const void* s) {
    asm volatile("cp.async.cg.shared.global [%0], [%1], 16;" :: "r"(d), "l"(s) : "memory");
}
__device__ __forceinline__ void cp_commit() { asm volatile("cp.async.commit_group;" ::: "memory"); }
__device__ __forceinline__ void cp_wait1()  { asm volatile("cp.async.wait_group 1;" ::: "memory"); }
__device__ __forceinline__ float4 ld_cg_f4(const float* p) {
    float4 v;
    asm volatile("ld.global.cg.v4.f32 {%0,%1,%2,%3}, [%4];"
                 : "=f"(v.x), "=f"(v.y), "=f"(v.z), "=f"(v.w) : "l"(p));
    return v;
}
__device__ __forceinline__ void st_cg_f4(float* p, float4 v) {
    asm volatile("st.global.cg.v4.f32 [%0], {%1,%2,%3,%4};"
                 :: "l"(p), "f"(v.x), "f"(v.y), "f"(v.z), "f"(v.w) : "memory");
}

// ------------- preprocessing -------------
// W [K, 4H] -> Wt[n=j*4+gate][k], split hi/lo fp16 (lo optional)
__global__ void split_w(const float* __restrict__ W, __half* __restrict__ oh,
                        __half* __restrict__ ol, int K)
{
    size_t i = (size_t)blockIdx.x * blockDim.x + threadIdx.x;
    int k = (int)(i % K), n = (int)(i / K);
    float x = W[(size_t)k * FH + (n & 3) * HH + (n >> 2)];
    __half h = __float2half(x);
    oh[i] = h;
    if (ol) ol[i] = __float2half(x - __half2float(h));
}
__global__ void interleave_bias(const float* __restrict__ b, float* __restrict__ bi)
{
    int n = blockIdx.x * blockDim.x + threadIdx.x;
    bi[n] = b[(n & 3) * HH + (n >> 2)];
}
__global__ void seq_sort(const int* __restrict__ seqlen)
{
    int b = threadIdx.x;
    int s = seqlen[b];
    int pos = 0;
    for (int j = 0; j < BB; j++) {
        int sj = seqlen[j];
        pos += (sj > s) || (sj == s && j < b);
    }
    d_pos[b] = pos;
    d_orig[pos] = b;
    d_seqP[pos] = s;
}
__global__ void seq_cnt(const int* __restrict__ seqlen)
{
    int t = threadIdx.x;
    if (t > TT) return;
    int c = 0;
    for (int j = 0; j < BB; j++) c += (seqlen[j] >= t + 1);
    d_cnt[t] = c;
}
__global__ void split_chars(const float* __restrict__ chars, __half* __restrict__ xh)
{
    int idx = blockIdx.x * blockDim.x + threadIdx.x;
    int d4 = idx & 63, rest = idx >> 6;
    int b = rest & (BB - 1), t = rest >> 9;
    float4 v = *(const float4*)(chars + ((size_t)b * TT + t) * DIN + d4 * 4);
    size_t o = ((size_t)t * BB + d_pos[b]) * DIN + d4 * 4;
    xh[o + 0] = __float2half(v.x);
    xh[o + 1] = __float2half(v.y);
    xh[o + 2] = __float2half(v.z);
    xh[o + 3] = __float2half(v.w);
}
__global__ void init_states()
{
    int i = blockIdx.x * blockDim.x + threadIdx.x;  // BB*HH threads
    d_c1[i] = 0.f; d_c2[i] = 0.f;
    __half z = __float2half(0.f);
    d_H1h[i] = z; d_H2h[i] = z;
    if (i < 4*TT*8) d_done[i] = 0;
    if (i == 0) d_ticket = 0;
}

// slot -> (role, step). roles: 0=l1, 1=w2, 2=l2, 3=w1. -1 if invalid.
__device__ __forceinline__ int slot_decode(int j, int* role)
{
    if (j < 4) { *role = 3; return j; }
    int t = (j - 4) >> 2, q = (j - 4) & 3;
    int r, s;
    if (q == 0)      { r = 3; s = t + 4; }
    else if (q == 1) { r = 0; s = t; }
    else if (q == 2) { r = 1; s = t - 1; }
    else             { r = 2; s = t - 2; }
    *role = r;
    return (s >= 0 && s < TT) ? s : -1;
}
__global__ void build_tiles()
{
    int id = blockIdx.x * blockDim.x + threadIdx.x;
    if (id >= NSLOT) return;
    int off = 0;
    for (int j = 0; j < id; j++) {
        int r, s = slot_decode(j, &r);
        if (s >= 0) off += ((d_cnt[s] + 63) >> 6) * 32;
    }
    if (id == 0) {
        int tot = 0;
        for (int j = 0; j < NSLOT; j++) {
            int r, s = slot_decode(j, &r);
            if (s >= 0) tot += ((d_cnt[s] + 63) >> 6) * 32;
        }
        d_ntiles = tot;
    }
    int role, step = slot_decode(id, &role);
    if (step < 0) return;
    int c = d_cnt[step];
    int ny = (c + 63) >> 6;
    for (int y = 0; y < ny; y++) {
        int half = (c <= y * 64 + 32) ? 1 : 0;
        for (int x = 0; x < 32; x++)
            d_tiles[off++] = x | (y << 5) | (step << 8) | (role << 15) | (half << 17);
    }
}
__global__ void dense_relu(const float* __restrict__ hidden, const float* __restrict__ Wd,
                           const float* __restrict__ bd, float* __restrict__ out)
{
    __shared__ float buf[3][128];
    int b = blockIdx.x, tid = threadIdx.x;
    const float* hb = hidden + (size_t)b * HH;
    float s0 = 0.f, s1 = 0.f, s2 = 0.f;
    for (int k = tid; k < HH; k += 128) {
        float hv = hb[k];
        s0 = fmaf(hv, Wd[k*3+0], s0); s1 = fmaf(hv, Wd[k*3+1], s1); s2 = fmaf(hv, Wd[k*3+2], s2);
    }
    buf[0][tid] = s0; buf[1][tid] = s1; buf[2][tid] = s2;
    __syncthreads();
    for (int s = 64; s > 0; s >>= 1) {
        if (tid < s) { buf[0][tid]+=buf[0][tid+s]; buf[1][tid]+=buf[1][tid+s]; buf[2][tid]+=buf[2][tid+s]; }
        __syncthreads();
    }
    if (tid < 3) out[b*3 + tid] = fmaxf(buf[tid][0] + bd[tid], 0.f);
}

// ------------- GEMM core, BM=64, NT weight terms -------------
// D[64,128] = A16[64,K] @ (Bh [+ Bl])[128,K]^T
// mode 0: Z[rowA,n] = D.  mode 1: z = D + Z + bias -> gates -> c, h(fp16).
template <int NT>
__device__ __forceinline__ void gemm_core(
    const __half* __restrict__ Ah,
    const __half* __restrict__ Bh, const __half* __restrict__ Bl,
    int K, float* __restrict__ Z, int mode,
    const float* __restrict__ biasI, float* __restrict__ cst,
    __half* __restrict__ hh,
    float* __restrict__ hidden, int step, int rbA, int rbB, char* smem)
{
    constexpr uint32_t STGN = ABYTES + NT * BBYTES;
    const int tid = threadIdx.x, wid = tid >> 5;
    const int wr = wid & 1, wc = wid >> 1;
    const int nch = K >> 5;
    const uint32_t sbase = smem_u32(smem);

    auto load_chunk = [&](int ch, int buf) {
        if (ch < nch) {
            const int k0 = ch << 5;
            const uint32_t st = sbase + (uint32_t)buf * STGN;
            {
                const __half* src = Ah + (size_t)rbA * K + k0;
                #pragma unroll
                for (int it = 0; it < 2; it++) {
                    int ck = it * 128 + tid;
                    int r = ck >> 2, c = ck & 3;
                    cp16(st + r * 80 + c * 16, src + (size_t)r * K + c * 8);
                }
            }
            const __half* sbp[2] = {Bh, Bl};
            #pragma unroll
            for (int op = 0; op < NT; op++) {
                const __half* src = sbp[op] + (size_t)rbB * K + k0;
                uint32_t sb = st + ABYTES + op * BBYTES;
                #pragma unroll
                for (int it = 0; it < 4; it++) {
                    int ck = it * 128 + tid;
                    int r = ck >> 2, c = ck & 3;
                    cp16(sb + r * 80 + c * 16, src + (size_t)r * K + c * 8);
                }
            }
        }
        cp_commit();
    };

    wmma::fragment<wmma::accumulator, 16, 16, 16, float> acc[2][4];
    #pragma unroll
    for (int m = 0; m < 2; m++)
        #pragma unroll
        for (int n = 0; n < 4; n++) wmma::fill_fragment(acc[m][n], 0.f);

    load_chunk(0, 0); load_chunk(1, 1);

    for (int i = 0; i < nch; i++) {
        cp_wait1();
        __syncthreads();
        load_chunk(i + 2, (i + 2) % NSTAGE);
        const __half* sb = (const __half*)(smem + (size_t)(i % NSTAGE) * STGN);
        const __half* sAh_ = sb;
        const __half* sBh_ = sb + 2560;
        const __half* sBl_ = sb + 7680;
        #pragma unroll
        for (int kk = 0; kk < 2; kk++) {
            wmma::fragment<wmma::matrix_a, 16, 16, 16, __half, wmma::row_major> fah[2];
            wmma::fragment<wmma::matrix_b, 16, 16, 16, __half, wmma::col_major> fbh[4], fbl[4];
            #pragma unroll
            for (int m = 0; m < 2; m++)
                wmma::load_matrix_sync(fah[m], sAh_ + (wr*32 + m*16)*40 + kk*16, 40);
            #pragma unroll
            for (int n = 0; n < 4; n++) {
                wmma::load_matrix_sync(fbh[n], sBh_ + (wc*64 + n*16)*40 + kk*16, 40);
                if (NT == 2)
                    wmma::load_matrix_sync(fbl[n], sBl_ + (wc*64 + n*16)*40 + kk*16, 40);
            }
            #pragma unroll
            for (int m = 0; m < 2; m++)
                #pragma unroll
                for (int n = 0; n < 4; n++) {
                    wmma::mma_sync(acc[m][n], fah[m], fbh[n], acc[m][n]);
                    if (NT == 2)
                        wmma::mma_sync(acc[m][n], fah[m], fbl[n], acc[m][n]);
                }
        }
    }

    if (mode == 0) {
        float* dst = Z + (size_t)rbA * FH + rbB;
        #pragma unroll
        for (int m = 0; m < 2; m++)
            #pragma unroll
            for (int n = 0; n < 4; n++)
                wmma::store_matrix_sync(dst + (size_t)(wr*32 + m*16) * FH + wc*64 + n*16,
                                        acc[m][n], FH, wmma::mem_row_major);
        return;
    }

    __syncthreads();
    float* Zs = (float*)smem;
    #pragma unroll
    for (int m = 0; m < 2; m++)
        #pragma unroll
        for (int n = 0; n < 4; n++)
            wmma::store_matrix_sync(Zs + (wr*32 + m*16) * LDS_EP + wc*64 + n*16,
                                    acc[m][n], LDS_EP, wmma::mem_row_major);
    __syncthreads();

    const int rl = tid >> 1, half = tid & 1;
    const int p = rbA + rl;
    const int n0 = rbB + half * 64;
    const int jb = n0 >> 2;
    const float* zs = Zs + rl * LDS_EP + half * 64;
    const float4* zg = (const float4*)(Z + (size_t)p * FH + n0);
    const float4* bi4 = (const float4*)(biasI + n0);
    float* crow = cst + (size_t)p * HH + jb;
    const bool gath = (hidden != nullptr) && (d_seqP[p] - 1 == step);
    float* hidrow = gath ? (hidden + (size_t)d_orig[p] * HH + jb) : nullptr;

    float cold[16];
    #pragma unroll
    for (int q = 0; q < 4; q++) {
        float4 cv = ld_cg_f4(crow + q*4);
        cold[q*4+0] = cv.x; cold[q*4+1] = cv.y; cold[q*4+2] = cv.z; cold[q*4+3] = cv.w;
    }
    float cn[16]; __half hb[16];
    #pragma unroll
    for (int g = 0; g < 16; g++) {
        float4 zv = zg[g], bv = bi4[g];
        float vi = zs[g*4+0] + zv.x + bv.x;
        float vf = zs[g*4+1] + zv.y + bv.y;
        float vg = zs[g*4+2] + zv.z + bv.z;
        float vo = zs[g*4+3] + zv.w + bv.w;
        float ig = 1.f / (1.f + __expf(-vi));
        float fg = 1.f / (1.f + __expf(-vf));
        float gg = tanhf(vg);
        float og = 1.f / (1.f + __expf(-vo));
        float c_ = fg * cold[g] + ig * gg;
        cn[g] = c_;
        float hv = og * tanhf(c_);
        hb[g] = __float2half(hv);
        if (gath) hidrow[g] = hv;
    }
    #pragma unroll
    for (int q = 0; q < 4; q++)
        st_cg_f4(crow + q*4, make_float4(cn[q*4], cn[q*4+1], cn[q*4+2], cn[q*4+3]));
    *(uint4*)(hh + (size_t)p * HH + jb)     = ((uint4*)hb)[0];
    *(uint4*)(hh + (size_t)p * HH + jb + 8) = ((uint4*)hb)[1];
}

// ------------- GEMM core, BM=32 (tail half-tiles), NT terms -------------
template <int NT>
__device__ __forceinline__ void gemm_core32(
    const __half* __restrict__ Ah,
    const __half* __restrict__ Bh, const __half* __restrict__ Bl,
    int K, float* __restrict__ Z, int mode,
    const float* __restrict__ biasI, float* __restrict__ cst,
    __half* __restrict__ hh,
    float* __restrict__ hidden, int step, int rbA, int rbB, char* smem)
{
    constexpr uint32_t STGN = 2560u + NT * BBYTES;
    const int tid = threadIdx.x, wid = tid >> 5;
    const int wc = wid;
    const int nch = K >> 5;
    const uint32_t sbase = smem_u32(smem);

    auto load_chunk = [&](int ch, int buf) {
        if (ch < nch) {
            const int k0 = ch << 5;
            const uint32_t st = sbase + (uint32_t)buf * STGN;
            {
                const __half* src = Ah + (size_t)rbA * K + k0;
                int r = tid >> 2, c = tid & 3;
                cp16(st + r * 80 + c * 16, src + (size_t)r * K + c * 8);
            }
            const __half* sbp[2] = {Bh, Bl};
            #pragma unroll
            for (int op = 0; op < NT; op++) {
                const __half* src = sbp[op] + (size_t)rbB * K + k0;
                uint32_t sb = st + 2560u + op * BBYTES;
                #pragma unroll
                for (int it = 0; it < 4; it++) {
                    int ck = it * 128 + tid;
                    int r = ck >> 2, c = ck & 3;
                    cp16(sb + r * 80 + c * 16, src + (size_t)r * K + c * 8);
                }
            }
        }
        cp_commit();
    };

    wmma::fragment<wmma::accumulator, 16, 16, 16, float> acc[2][2];
    #pragma unroll
    for (int m = 0; m < 2; m++)
        #pragma unroll
        for (int n = 0; n < 2; n++) wmma::fill_fragment(acc[m][n], 0.f);

    load_chunk(0, 0); load_chunk(1, 1);

    for (int i = 0; i < nch; i++) {
        cp_wait1();
        __syncthreads();
        load_chunk(i + 2, (i + 2) % NSTAGE);
        const __half* sb = (const __half*)(smem + (size_t)(i % NSTAGE) * STGN);
        const __half* sAh_ = sb;
        const __half* sBh_ = sb + 1280;
        const __half* sBl_ = sb + 6400;
        #pragma unroll
        for (int kk = 0; kk < 2; kk++) {
            wmma::fragment<wmma::matrix_a, 16, 16, 16, __half, wmma::row_major> fah[2];
            wmma::fragment<wmma::matrix_b, 16, 16, 16, __half, wmma::col_major> fbh[2], fbl[2];
            #pragma unroll
            for (int m = 0; m < 2; m++)
                wmma::load_matrix_sync(fah[m], sAh_ + (m*16)*40 + kk*16, 40);
            #pragma unroll
            for (int n = 0; n < 2; n++) {
                wmma::load_matrix_sync(fbh[n], sBh_ + (wc*32 + n*16)*40 + kk*16, 40);
                if (NT == 2)
                    wmma::load_matrix_sync(fbl[n], sBl_ + (wc*32 + n*16)*40 + kk*16, 40);
            }
            #pragma unroll
            for (int m = 0; m < 2; m++)
                #pragma unroll
                for (int n = 0; n < 2; n++) {
                    wmma::mma_sync(acc[m][n], fah[m], fbh[n], acc[m][n]);
                    if (NT == 2)
                        wmma::mma_sync(acc[m][n], fah[m], fbl[n], acc[m][n]);
                }
        }
    }

    if (mode == 0) {
        float* dst = Z + (size_t)rbA * FH + rbB;
        #pragma unroll
        for (int m = 0; m < 2; m++)
            #pragma unroll
            for (int n = 0; n < 2; n++)
                wmma::store_matrix_sync(dst + (size_t)(m*16) * FH + wc*32 + n*16,
                                        acc[m][n], FH, wmma::mem_row_major);
        return;
    }

    __syncthreads();
    float* Zs = (float*)smem;
    #pragma unroll
    for (int m = 0; m < 2; m++)
        #pragma unroll
        for (int n = 0; n < 2; n++)
            wmma::store_matrix_sync(Zs + (m*16) * LDS_EP + wc*32 + n*16,
                                    acc[m][n], LDS_EP, wmma::mem_row_major);
    __syncthreads();

    const int rl = tid >> 2, q4 = tid & 3;
    const int p = rbA + rl;
    const int n0 = rbB + q4 * 32;
    const int jb = n0 >> 2;
    const float* zs = Zs + rl * LDS_EP + q4 * 32;
    const float4* zg = (const float4*)(Z + (size_t)p * FH + n0);
    const float4* bi4 = (const float4*)(biasI + n0);
    float* crow = cst + (size_t)p * HH + jb;
    const bool gath = (hidden != nullptr) && (d_seqP[p] - 1 == step);
    float* hidrow = gath ? (hidden + (size_t)d_orig[p] * HH + jb) : nullptr;

    float cold[8];
    #pragma unroll
    for (int q = 0; q < 2; q++) {
        float4 cv = ld_cg_f4(crow + q*4);
        cold[q*4+0] = cv.x; cold[q*4+1] = cv.y; cold[q*4+2] = cv.z; cold[q*4+3] = cv.w;
    }
    float cn[8]; __half hb[8];
    #pragma unroll
    for (int g = 0; g < 8; g++) {
        float4 zv = zg[g], bv = bi4[g];
        float vi = zs[g*4+0] + zv.x + bv.x;
        float vf = zs[g*4+1] + zv.y + bv.y;
        float vg = zs[g*4+2] + zv.z + bv.z;
        float vo = zs[g*4+3] + zv.w + bv.w;
        float ig = 1.f / (1.f + __expf(-vi));
        float fg = 1.f / (1.f + __expf(-vf));
        float gg = tanhf(vg);
        float og = 1.f / (1.f + __expf(-vo));
        float c_ = fg * cold[g] + ig * gg;
        cn[g] = c_;
        float hv = og * tanhf(c_);
        hb[g] = __float2half(hv);
        if (gath) hidrow[g] = hv;
    }
    #pragma unroll
    for (int q = 0; q < 2; q++)
        st_cg_f4(crow + q*4, make_float4(cn[q*4], cn[q*4+1], cn[q*4+2], cn[q*4+3]));
    *(uint4*)(hh + (size_t)p * HH + jb) = ((uint4*)hb)[0];
}

// ------------- persistent worker -------------
__device__ __forceinline__ void wait_flag(int idx) {
    volatile int* f = (volatile int*)d_done;
    while (f[idx] < 32) __nanosleep(256);
}

__global__ void __launch_bounds__(128, 2)
worker(const __half* __restrict__ U1h, const __half* __restrict__ U1l,
       const __half* __restrict__ W2h,
       const __half* __restrict__ U2h, const __half* __restrict__ U2l,
       const __half* __restrict__ W1h,
       const __half* __restrict__ Xh,
       __half* __restrict__ H1h, __half* __restrict__ H2h,
       float* __restrict__ Z1, float* __restrict__ Z2,
       const float* __restrict__ b1i, const float* __restrict__ b2i,
       float* __restrict__ c1, float* __restrict__ c2,
       float* __restrict__ hidden)
{
    extern __shared__ char smem[];
    __shared__ int s_w;
    const int tid = threadIdx.x;
    const size_t HB = (size_t)BB * HH;

    for (;;) {
        __syncthreads();
        if (tid == 0) {
            int k = atomicAdd(&d_ticket, 1);
            s_w = (k < d_ntiles) ? d_tiles[k] : -1;
        }
        __syncthreads();
        const int w = s_w;
        if (w < 0) break;
        const int x = w & 31, y = (w >> 5) & 7, step = (w >> 8) & 127;
        const int role = (w >> 15) & 3, halfT = (w >> 17) & 1;

        if (tid == 0) {
            if (role == 0) {
                if (step > 0) wait_flag(0*TT*8 + (step-1)*8 + y);
                wait_flag(3*TT*8 + step*8 + y);
            } else if (role == 1) {
                wait_flag(0*TT*8 + step*8 + y);
            } else if (role == 2) {
                wait_flag(1*TT*8 + step*8 + y);
                if (step > 0) wait_flag(2*TT*8 + (step-1)*8 + y);
            }
            __threadfence();
        }
        __syncthreads();

        const int rbB = x * BN;
        if (role == 0) {          // layer-1 recurrent step: 2-term U1
            const int rbA = y * BM;
            float* Zp = Z1 + (size_t)step * BB * FH;
            __half* oh = H1h + (size_t)(step+1) * HB;
            if (halfT)
                gemm_core32<2>(H1h + (size_t)step * HB, U1h, U1l, HH, Zp, 1,
                               b1i, c1, oh, nullptr, step, rbA, rbB, smem);
            else
                gemm_core<2>(H1h + (size_t)step * HB, U1h, U1l, HH, Zp, 1,
                             b1i, c1, oh, nullptr, step, rbA, rbB, smem);
        } else if (role == 1) {   // W2 input-transform slice: 1-term W2
            const int rbA = y * BM;
            float* Zp = Z2 + (size_t)step * BB * FH;
            if (halfT)
                gemm_core32<1>(H1h + (size_t)(step+1) * HB, W2h, W2h, HH, Zp, 0,
                               nullptr, nullptr, nullptr, nullptr, step, rbA, rbB, smem);
            else
                gemm_core<1>(H1h + (size_t)(step+1) * HB, W2h, W2h, HH, Zp, 0,
                             nullptr, nullptr, nullptr, nullptr, step, rbA, rbB, smem);
        } else if (role == 2) {   // layer-2 recurrent step + gather: 2-term U2
            const int rbA = y * BM;
            float* Zp = Z2 + (size_t)step * BB * FH;
            __half* oh = H2h + (size_t)(step+1) * HB;
            if (halfT)
                gemm_core32<2>(H2h + (size_t)step * HB, U2h, U2l, HH, Zp, 1,
                               b2i, c2, oh, hidden, step, rbA, rbB, smem);
            else
                gemm_core<2>(H2h + (size_t)step * HB, U2h, U2l, HH, Zp, 1,
                             b2i, c2, oh, hidden, step, rbA, rbB, smem);
        } else {                  // W1 input-transform slice: 1-term W1
            const int rbA = step * BB + y * BM;
            if (halfT)
                gemm_core32<1>(Xh, W1h, W1h, DIN, Z1, 0,
                               nullptr, nullptr, nullptr, nullptr, step, rbA, rbB, smem);
            else
                gemm_core<1>(Xh, W1h, W1h, DIN, Z1, 0,
                             nullptr, nullptr, nullptr, nullptr, step, rbA, rbB, smem);
        }

        __threadfence();
        __syncthreads();
        if (tid == 0) atomicAdd(&d_done[role*TT*8 + step*8 + y], 1);
    }
}

// ------------- launch -------------
extern "C" void kernel_launch(void* const* d_in, const int* in_sizes, int n_in,
                              void* d_out, int out_size)
{
    const float* chars  = (const float*)d_in[0];
    const int*   seqlen = (const int*)  d_in[1];
    const float* W1 = (const float*)d_in[2];
    const float* U1 = (const float*)d_in[3];
    const float* b1 = (const float*)d_in[4];
    const float* W2 = (const float*)d_in[5];
    const float* U2 = (const float*)d_in[6];
    const float* b2 = (const float*)d_in[7];
    const float* Wd = (const float*)d_in[8];
    const float* bd = (const float*)d_in[9];
    float* out = (float*)d_out;

    cudaFuncSetAttribute(worker, cudaFuncAttributeMaxDynamicSharedMemorySize, SMEM_DYN);

    float *Z1, *Z2, *c1, *c2, *hidden, *b1i, *b2i;
    __half *Xh, *H1h, *H2h;
    __half *W1h, *U1h, *U1l, *W2h, *U2h, *U2l;
    cudaGetSymbolAddress((void**)&Z1, d_Z1);   cudaGetSymbolAddress((void**)&Z2, d_Z2);
    cudaGetSymbolAddress((void**)&c1, d_c1);   cudaGetSymbolAddress((void**)&c2, d_c2);
    cudaGetSymbolAddress((void**)&hidden, d_hidden);
    cudaGetSymbolAddress((void**)&b1i, d_b1i); cudaGetSymbolAddress((void**)&b2i, d_b2i);
    cudaGetSymbolAddress((void**)&Xh, d_Xh);
    cudaGetSymbolAddress((void**)&H1h, d_H1h);
    cudaGetSymbolAddress((void**)&H2h, d_H2h);
    cudaGetSymbolAddress((void**)&W1h, d_W1h);
    cudaGetSymbolAddress((void**)&U1h, d_U1h); cudaGetSymbolAddress((void**)&U1l, d_U1l);
    cudaGetSymbolAddress((void**)&W2h, d_W2h);
    cudaGetSymbolAddress((void**)&U2h, d_U2h); cudaGetSymbolAddress((void**)&U2l, d_U2l);

    split_w<<<(FH*DIN)/256, 256>>>(W1, W1h, nullptr, DIN);
    split_w<<<(FH*HH)/256, 256>>>(U1, U1h, U1l, HH);
    split_w<<<(FH*HH)/256, 256>>>(W2, W2h, nullptr, HH);
    split_w<<<(FH*HH)/256, 256>>>(U2, U2h, U2l, HH);
    interleave_bias<<<FH/256, 256>>>(b1, b1i);
    interleave_bias<<<FH/256, 256>>>(b2, b2i);
    seq_sort<<<1, BB>>>(seqlen);
    seq_cnt<<<1, TT+1>>>(seqlen);
    split_chars<<<(TBROWS*64)/256, 256>>>(chars, Xh);
    init_states<<<(BB*HH)/256, 256>>>();
    build_tiles<<<3, 256>>>();

    worker<<<NWORKER, 128, SMEM_DYN>>>(U1h, U1l, W2h, U2h, U2l,
                                       W1h, Xh,
                                       H1h, H2h, Z1, Z2,
                                       b1i, b2i, c1, c2, hidden);

    dense_relu<<<BB, 128>>>(hidden, Wd, bd, out);
}